// round 2
// baseline (speedup 1.0000x reference)
#include <cuda_runtime.h>

#define HD 256
#define NMAX 50048
#define EMAX 800000
#define NGR 64
typedef unsigned long long ull;

// ---------------- device scratch (static, no runtime alloc) ----------------
__device__ float g_agg [(size_t)NMAX * HD];
__device__ float g_hbuf[(size_t)NMAX * HD];
__device__ float g_xa  [(size_t)NMAX * HD];
__device__ float g_xb  [(size_t)NMAX * HD];
__device__ int   g_src [EMAX];
__device__ int   g_dstv[EMAX];
__device__ int   g_nbr [EMAX];
__device__ int   g_deg [NMAX];
__device__ int   g_off [NMAX + 1];
__device__ int   g_cur [NMAX];
__device__ int   g_batch[NMAX];
__device__ int   g_bsum[1024];
__device__ int   g_bpre[1024];
__device__ float g_colsum[HD];
__device__ float g_colsq [HD];
__device__ float g_pool[NGR * HD];
__device__ float g_cnt [NGR];
__device__ int   g_flags[2];

// ---------------- dtype sniffing + index normalization ----------------
__global__ void k_detect(const int* __restrict__ ei, const int* __restrict__ bat, int N)
{
    if (threadIdx.x == 0 && blockIdx.x == 0) {
        int e64 = (ei[1] == 0 && ei[3] == 0 && ei[5] == 0 && ei[7] == 0) ? 1 : 0;
        int w = N - 1; if (!(w & 1)) w--;
        int b64 = (bat[w] == 0) ? 1 : 0;
        g_flags[0] = e64;
        g_flags[1] = b64;
    }
}

__global__ void k_convert(const int* __restrict__ ei, const int* __restrict__ bat, int E, int N)
{
    int i = blockIdx.x * blockDim.x + threadIdx.x;
    int e64 = g_flags[0], b64 = g_flags[1];
    if (i < E) {
        if (e64) { g_src[i] = ei[2 * i]; g_dstv[i] = ei[2 * (E + i)]; }
        else     { g_src[i] = ei[i];     g_dstv[i] = ei[E + i]; }
    }
    if (i < N) {
        g_batch[i] = b64 ? bat[2 * i] : bat[i];
        g_deg[i] = 0;
    }
}

// ---------------- CSR build (by dst) ----------------
__global__ void k_count(int E)
{
    int i = blockIdx.x * blockDim.x + threadIdx.x;
    if (i < E) atomicAdd(&g_deg[g_dstv[i]], 1);
}

// fast 3-phase scan: per-block sums -> 1-block scan of partials -> per-block scan
__global__ void k_bsum(int N)
{
    int t = threadIdx.x;
    int i = blockIdx.x * 256 + t;
    int v = (i < N) ? g_deg[i] : 0;
#pragma unroll
    for (int o = 16; o; o >>= 1) v += __shfl_down_sync(~0u, v, o);
    __shared__ int ws[8];
    if ((t & 31) == 0) ws[t >> 5] = v;
    __syncthreads();
    if (t == 0) {
        int s = 0;
#pragma unroll
        for (int k = 0; k < 8; k++) s += ws[k];
        g_bsum[blockIdx.x] = s;
    }
}

__global__ void k_bscan(int nb)
{
    __shared__ int sm[256];
    int t = threadIdx.x;
    int v = (t < nb) ? g_bsum[t] : 0;
    sm[t] = v;
    __syncthreads();
    for (int o = 1; o < 256; o <<= 1) {
        int a = (t >= o) ? sm[t - o] : 0;
        __syncthreads();
        sm[t] += a;
        __syncthreads();
    }
    g_bpre[t] = sm[t] - v;   // exclusive
}

__global__ void k_off(int N)
{
    int t = threadIdx.x;
    int i = blockIdx.x * 256 + t;
    int v = (i < N) ? g_deg[i] : 0;
    int lane = t & 31, wid = t >> 5;
    int x = v;
#pragma unroll
    for (int o = 1; o < 32; o <<= 1) {
        int y = __shfl_up_sync(~0u, x, o);
        if (lane >= o) x += y;
    }
    __shared__ int ws[8];
    if (lane == 31) ws[wid] = x;
    __syncthreads();
    if (t < 8) {
        int y = ws[t];
#pragma unroll
        for (int o = 1; o < 8; o <<= 1) {
            int z = __shfl_up_sync(0xff, y, o);
            if (t >= o) y += z;
        }
        ws[t] = y;
    }
    __syncthreads();
    int incl = x + (wid ? ws[wid - 1] : 0);
    int off = g_bpre[blockIdx.x] + incl - v;
    if (i < N) { g_off[i] = off; g_cur[i] = off; }
    if (i == N - 1) g_off[N] = off + v;
}

__global__ void k_fill(int E)
{
    int i = blockIdx.x * blockDim.x + threadIdx.x;
    if (i < E) {
        int d = g_dstv[i];
        int p = atomicAdd(&g_cur[d], 1);
        g_nbr[p] = g_src[i];
    }
}

// ---------------- GIN aggregation: out[i] = x[i] + sum_{j in N(i)} x[j] ----------------
__global__ void k_gather128(const float* __restrict__ xin, float* __restrict__ out, int N)
{
    if (blockIdx.x == 0) { g_colsum[threadIdx.x] = 0.f; g_colsq[threadIdx.x] = 0.f; }
    int gt = blockIdx.x * blockDim.x + threadIdx.x;
    int w = gt >> 5, lane = gt & 31;
    if (w >= N) return;
    const float4* xp = (const float4*)xin;
    float4 a = xp[(size_t)w * 32 + lane];
    int e = g_off[w], e1 = g_off[w + 1];
    for (; e + 1 < e1; e += 2) {
        int n0 = g_nbr[e], n1 = g_nbr[e + 1];
        float4 v0 = xp[(size_t)n0 * 32 + lane];
        float4 v1 = xp[(size_t)n1 * 32 + lane];
        a.x += v0.x; a.y += v0.y; a.z += v0.z; a.w += v0.w;
        a.x += v1.x; a.y += v1.y; a.z += v1.z; a.w += v1.w;
    }
    if (e < e1) {
        float4 v = xp[(size_t)g_nbr[e] * 32 + lane];
        a.x += v.x; a.y += v.y; a.z += v.z; a.w += v.w;
    }
    ((float4*)out)[(size_t)w * 32 + lane] = a;
}

__global__ void k_gather256(const float* __restrict__ xin, float* __restrict__ out, int N)
{
    if (blockIdx.x == 0) { g_colsum[threadIdx.x] = 0.f; g_colsq[threadIdx.x] = 0.f; }
    int gt = blockIdx.x * blockDim.x + threadIdx.x;
    int w = gt >> 5, lane = gt & 31;
    if (w >= N) return;
    const float4* xp = (const float4*)xin;
    float4 a0 = xp[(size_t)w * 64 + lane];
    float4 a1 = xp[(size_t)w * 64 + 32 + lane];
    int e = g_off[w], e1 = g_off[w + 1];
    for (; e + 1 < e1; e += 2) {
        size_t b0 = (size_t)g_nbr[e] * 64;
        size_t b1 = (size_t)g_nbr[e + 1] * 64;
        float4 u0 = xp[b0 + lane];
        float4 u1 = xp[b0 + 32 + lane];
        float4 w0 = xp[b1 + lane];
        float4 w1 = xp[b1 + 32 + lane];
        a0.x += u0.x; a0.y += u0.y; a0.z += u0.z; a0.w += u0.w;
        a1.x += u1.x; a1.y += u1.y; a1.z += u1.z; a1.w += u1.w;
        a0.x += w0.x; a0.y += w0.y; a0.z += w0.z; a0.w += w0.w;
        a1.x += w1.x; a1.y += w1.y; a1.z += w1.z; a1.w += w1.w;
    }
    if (e < e1) {
        size_t b = (size_t)g_nbr[e] * 64;
        float4 v0 = xp[b + lane];
        float4 v1 = xp[b + 32 + lane];
        a0.x += v0.x; a0.y += v0.y; a0.z += v0.z; a0.w += v0.w;
        a1.x += v1.x; a1.y += v1.y; a1.z += v1.z; a1.w += v1.w;
    }
    ((float4*)out)[(size_t)w * 64 + lane]      = a0;
    ((float4*)out)[(size_t)w * 64 + 32 + lane] = a1;
}

// ---------------- GEMM via packed fma.rn.f32x2 ----------------
// H = A[M,K] @ W[K,256] + b, fused column sum/sumsq for BN.
// Accumulators pair adjacent M-rows in one b64 reg; B stored DUPLICATED in
// shared so both FFMA2 operands come straight out of LDS.128 (no pack MOVs).
template <int K>
__launch_bounds__(256, 2)
__global__ void k_gemm(const float* __restrict__ A, const float* __restrict__ W,
                       const float* __restrict__ bias, float* __restrict__ Hout, int M)
{
    const int BM = 128, BN = 128, BK = 16;
    __shared__ float As[BK][132];
    __shared__ float Bsd[BK][256];       // duplicated: [2c]=[2c+1]=W[.,bn+c]
    __shared__ float Red[16][BN];
    int bm = blockIdx.x * BM, bn = blockIdx.y * BN;
    int t = threadIdx.x;
    int tx = t & 15, ty = t >> 4;

    ull acc2[4][8];                       // [rowpair][col], lanes = (row even, row odd)
#pragma unroll
    for (int i = 0; i < 4; i++)
#pragma unroll
        for (int j = 0; j < 8; j++) acc2[i][j] = 0ull;

    for (int k0 = 0; k0 < K; k0 += BK) {
#pragma unroll
        for (int s = 0; s < 2; s++) {
            int f = t + s * 256;
            int row = f >> 2;
            int c4 = f & 3;
            int gr = bm + row;
            float4 v = make_float4(0.f, 0.f, 0.f, 0.f);
            if (gr < M) v = *(const float4*)(A + (size_t)gr * K + k0 + c4 * 4);
            As[c4 * 4 + 0][row] = v.x;
            As[c4 * 4 + 1][row] = v.y;
            As[c4 * 4 + 2][row] = v.z;
            As[c4 * 4 + 3][row] = v.w;
        }
#pragma unroll
        for (int s = 0; s < 4; s++) {
            int u = t + s * 256;          // 0..1023
            int row = u >> 6;             // 16 rows
            int cp = u & 63;              // 64 column-pairs
            float2 w = *(const float2*)(W + (size_t)(k0 + row) * HD + bn + cp * 2);
            *(float4*)&Bsd[row][cp * 4] = make_float4(w.x, w.x, w.y, w.y);
        }
        __syncthreads();
#pragma unroll
        for (int kk = 0; kk < BK; kk++) {
            ulonglong2 av0 = *(const ulonglong2*)&As[kk][ty * 8];
            ulonglong2 av1 = *(const ulonglong2*)&As[kk][ty * 8 + 4];
            ulonglong2 bv0 = *(const ulonglong2*)&Bsd[kk][tx * 16];
            ulonglong2 bv1 = *(const ulonglong2*)&Bsd[kk][tx * 16 + 4];
            ulonglong2 bv2 = *(const ulonglong2*)&Bsd[kk][tx * 16 + 8];
            ulonglong2 bv3 = *(const ulonglong2*)&Bsd[kk][tx * 16 + 12];
            ull ap[4] = { av0.x, av0.y, av1.x, av1.y };
            ull bp[8] = { bv0.x, bv0.y, bv1.x, bv1.y, bv2.x, bv2.y, bv3.x, bv3.y };
#pragma unroll
            for (int ip = 0; ip < 4; ip++)
#pragma unroll
                for (int j = 0; j < 8; j++)
                    asm("fma.rn.f32x2 %0, %1, %2, %0;"
                        : "+l"(acc2[ip][j]) : "l"(ap[ip]), "l"(bp[j]));
        }
        __syncthreads();
    }

    // unpack accumulators
    float accf[8][8];
#pragma unroll
    for (int ip = 0; ip < 4; ip++)
#pragma unroll
        for (int j = 0; j < 8; j++) {
            float lo, hi;
            asm("mov.b64 {%0,%1}, %2;" : "=f"(lo), "=f"(hi) : "l"(acc2[ip][j]));
            accf[2 * ip][j] = lo;
            accf[2 * ip + 1][j] = hi;
        }

    // epilogue: bias, store, per-column sum/sumsq for BN
    float bv[8], cs[8], cq[8];
#pragma unroll
    for (int j = 0; j < 8; j++) { bv[j] = bias[bn + tx * 8 + j]; cs[j] = 0.f; cq[j] = 0.f; }
#pragma unroll
    for (int i = 0; i < 8; i++) {
        int gr = bm + ty * 8 + i;
        if (gr < M) {
            float o[8];
#pragma unroll
            for (int j = 0; j < 8; j++) {
                float v = accf[i][j] + bv[j];
                o[j] = v; cs[j] += v; cq[j] += v * v;
            }
            float* dst = Hout + (size_t)gr * HD + bn + tx * 8;
            *(float4*)dst       = make_float4(o[0], o[1], o[2], o[3]);
            *(float4*)(dst + 4) = make_float4(o[4], o[5], o[6], o[7]);
        }
    }
#pragma unroll
    for (int j = 0; j < 8; j++) Red[ty][tx * 8 + j] = cs[j];
    __syncthreads();
    if (t < BN) {
        float s = 0.f;
#pragma unroll
        for (int r = 0; r < 16; r++) s += Red[r][t];
        atomicAdd(&g_colsum[bn + t], s);
    }
    __syncthreads();
#pragma unroll
    for (int j = 0; j < 8; j++) Red[ty][tx * 8 + j] = cq[j];
    __syncthreads();
    if (t < BN) {
        float s = 0.f;
#pragma unroll
        for (int r = 0; r < 16; r++) s += Red[r][t];
        atomicAdd(&g_colsq[bn + t], s);
    }
}

// ---------------- BN (train-mode, biased var) + ReLU (+ residual) ----------------
__global__ void k_bnrelu(const float* __restrict__ Hin, const float* __restrict__ gam,
                         const float* __restrict__ bet, const float* __restrict__ resid,
                         float* __restrict__ out, int M)
{
    size_t idx = (size_t)blockIdx.x * blockDim.x + threadIdx.x;
    size_t tot = (size_t)M * (HD / 4);
    if (idx >= tot) return;
    int c4 = (int)(idx & 63);
    float invN = 1.0f / (float)M;
    float4 h = ((const float4*)Hin)[idx];
    float hv[4] = { h.x, h.y, h.z, h.w };
    float o[4];
#pragma unroll
    for (int j = 0; j < 4; j++) {
        int c = c4 * 4 + j;
        float m = g_colsum[c] * invN;
        float v = fmaf(-m, m, g_colsq[c] * invN);
        float sc = gam[c] * rsqrtf(v + 1e-5f);
        float sh = fmaf(-m, sc, bet[c]);
        o[j] = fmaxf(fmaf(hv[j], sc, sh), 0.0f);
    }
    if (resid) {
        float4 rr = ((const float4*)resid)[idx];
        o[0] += rr.x; o[1] += rr.y; o[2] += rr.z; o[3] += rr.w;
    }
    ((float4*)out)[idx] = make_float4(o[0], o[1], o[2], o[3]);
}

// ---------------- pool: batch is sorted -> register-accumulate, flush on change ----------------
__global__ void k_pool2(const float* __restrict__ x3, int N)
{
    __shared__ int sb[128];
    int n0 = blockIdx.x * 128;
    int n1 = n0 + 128; if (n1 > N) n1 = N;
    int t = threadIdx.x;                  // 256 threads, one column each
    if (t < n1 - n0) sb[t] = g_batch[n0 + t];
    __syncthreads();
    if (n1 <= n0) return;
    float acc = 0.f;
    int curg = sb[0], cnt = 0;
    for (int n = n0; n < n1; n++) {
        int g = sb[n - n0];
        if (g != curg) {
            atomicAdd(&g_pool[curg * HD + t], acc);
            if (t == 0) atomicAdd(&g_cnt[curg], (float)cnt);
            acc = 0.f; cnt = 0; curg = g;
        }
        acc += x3[(size_t)n * HD + t];
        cnt++;
    }
    atomicAdd(&g_pool[curg * HD + t], acc);
    if (t == 0) atomicAdd(&g_cnt[curg], (float)cnt);
}

// ---------------- final MLP head (64 graphs) ----------------
__global__ void k_final(const float* __restrict__ fcW1, const float* __restrict__ fcb1,
                        const float* __restrict__ fcW2, const float* __restrict__ fcb2,
                        float* __restrict__ out)
{
    __shared__ float prow[HD];
    __shared__ float hred[HD];
    int g = blockIdx.x, t = threadIdx.x;
    float cnt = fmaxf(g_cnt[g], 1.0f);
    prow[t] = g_pool[g * HD + t] / cnt;
    __syncthreads();
    float acc = fcb1[t];
    for (int k = 0; k < HD; k++)
        acc = fmaf(prow[k], __ldg(fcW1 + (size_t)k * HD + t), acc);
    float h = fmaxf(acc, 0.0f);
    hred[t] = h * fcW2[t];
    __syncthreads();
    for (int s = HD / 2; s > 0; s >>= 1) {
        if (t < s) hred[t] += hred[t + s];
        __syncthreads();
    }
    if (t == 0) out[g] = hred[0] + fcb2[0];
}

// ---------------- launch ----------------
extern "C" void kernel_launch(void* const* d_in, const int* in_sizes, int n_in,
                              void* d_out, int out_size)
{
    int base = 3;
    if (n_in >= 20 && in_sizes[3] == 1) base = 4;

    const float* x   = (const float*)d_in[0];
    const int*   ei  = (const int*)d_in[1];
    const int*   bat = (const int*)d_in[2];
    const float* W1  = (const float*)d_in[base + 0];
    const float* b1  = (const float*)d_in[base + 1];
    const float* W2  = (const float*)d_in[base + 2];
    const float* b2  = (const float*)d_in[base + 3];
    const float* W3  = (const float*)d_in[base + 4];
    const float* b3  = (const float*)d_in[base + 5];
    const float* ga1 = (const float*)d_in[base + 6];
    const float* be1 = (const float*)d_in[base + 7];
    const float* ga2 = (const float*)d_in[base + 8];
    const float* be2 = (const float*)d_in[base + 9];
    const float* ga3 = (const float*)d_in[base + 10];
    const float* be3 = (const float*)d_in[base + 11];
    const float* fcW1 = (const float*)d_in[base + 12];
    const float* fcb1 = (const float*)d_in[base + 13];
    const float* fcW2 = (const float*)d_in[base + 14];
    const float* fcb2 = (const float*)d_in[base + 15];

    int N = in_sizes[0] / 128;
    int E = in_sizes[1] / 2;

    void* p;
    float *agg, *hbuf, *xa, *xb;
    cudaGetSymbolAddress(&p, g_agg);  agg  = (float*)p;
    cudaGetSymbolAddress(&p, g_hbuf); hbuf = (float*)p;
    cudaGetSymbolAddress(&p, g_xa);   xa   = (float*)p;
    cudaGetSymbolAddress(&p, g_xb);   xb   = (float*)p;
    void *ppool, *pcnt;
    cudaGetSymbolAddress(&ppool, g_pool);
    cudaGetSymbolAddress(&pcnt,  g_cnt);

    const int tb = 256;
    int ebl = (E + tb - 1) / tb;
    int nb256 = (N + 255) / 256;
    int wbl = (N * 32 + tb - 1) / tb;
    int bnbl = (int)(((size_t)N * (HD / 4) + tb - 1) / tb);
    dim3 ggrid((N + 127) / 128, 2);

    // index normalization + CSR (shared by all 3 layers)
    k_detect<<<1, 32>>>(ei, bat, N);
    k_convert<<<ebl, tb>>>(ei, bat, E, N);
    k_count<<<ebl, tb>>>(E);
    k_bsum<<<nb256, 256>>>(N);
    k_bscan<<<1, 256>>>(nb256);
    k_off<<<nb256, 256>>>(N);
    k_fill<<<ebl, tb>>>(E);

    // layer 1: K=128
    k_gather128<<<wbl, tb>>>(x, agg, N);
    k_gemm<128><<<ggrid, 256>>>(agg, W1, b1, hbuf, N);
    k_bnrelu<<<bnbl, tb>>>(hbuf, ga1, be1, nullptr, xa, N);

    // layer 2
    k_gather256<<<wbl, tb>>>(xa, agg, N);
    k_gemm<256><<<ggrid, 256>>>(agg, W2, b2, hbuf, N);
    k_bnrelu<<<bnbl, tb>>>(hbuf, ga2, be2, xa, xb, N);

    // layer 3
    k_gather256<<<wbl, tb>>>(xb, agg, N);
    k_gemm<256><<<ggrid, 256>>>(agg, W3, b3, hbuf, N);
    k_bnrelu<<<bnbl, tb>>>(hbuf, ga3, be3, xb, xa, N);

    // pool + head
    cudaMemsetAsync(ppool, 0, NGR * HD * sizeof(float));
    cudaMemsetAsync(pcnt, 0, NGR * sizeof(float));
    k_pool2<<<(N + 127) / 128, 256>>>(xa, N);
    k_final<<<NGR, 256>>>(fcW1, fcb1, fcW2, fcb2, (float*)d_out);
}

// round 3
// speedup vs baseline: 2.4976x; 2.4976x over previous
#include <cuda_runtime.h>
#include <stdint.h>

#define HD 256
#define NMAX 50048
#define EMAX 800000
#define NGR 64

// ---------------- device scratch (static, no runtime alloc) ----------------
__device__ float g_agg [(size_t)NMAX * HD];
__device__ float g_hbuf[(size_t)NMAX * HD];
__device__ float g_xa  [(size_t)NMAX * HD];
__device__ float g_xb  [(size_t)NMAX * HD];
__device__ int   g_src [EMAX];
__device__ int   g_dstv[EMAX];
__device__ int   g_nbr [EMAX];
__device__ int   g_deg [NMAX];
__device__ int   g_off [NMAX + 1];
__device__ int   g_cur [NMAX];
__device__ int   g_batch[NMAX];
__device__ int   g_bsum[1024];
__device__ int   g_bpre[1024];
__device__ float g_colsum[HD];
__device__ float g_colsq [HD];
__device__ float g_pool[NGR * HD];
__device__ float g_cnt [NGR];
__device__ int   g_flags[2];

// ---------------- dtype sniffing + index normalization ----------------
__global__ void k_detect(const int* __restrict__ ei, const int* __restrict__ bat, int N)
{
    if (threadIdx.x == 0 && blockIdx.x == 0) {
        int e64 = (ei[1] == 0 && ei[3] == 0 && ei[5] == 0 && ei[7] == 0) ? 1 : 0;
        int w = N - 1; if (!(w & 1)) w--;
        int b64 = (bat[w] == 0) ? 1 : 0;
        g_flags[0] = e64;
        g_flags[1] = b64;
    }
}

__global__ void k_convert(const int* __restrict__ ei, const int* __restrict__ bat, int E, int N)
{
    int i = blockIdx.x * blockDim.x + threadIdx.x;
    int e64 = g_flags[0], b64 = g_flags[1];
    if (i < E) {
        if (e64) { g_src[i] = ei[2 * i]; g_dstv[i] = ei[2 * (E + i)]; }
        else     { g_src[i] = ei[i];     g_dstv[i] = ei[E + i]; }
    }
    if (i < N) {
        g_batch[i] = b64 ? bat[2 * i] : bat[i];
        g_deg[i] = 0;
    }
}

// ---------------- CSR build (by dst) ----------------
__global__ void k_count(int E)
{
    int i = blockIdx.x * blockDim.x + threadIdx.x;
    if (i < E) atomicAdd(&g_deg[g_dstv[i]], 1);
}

__global__ void k_bsum(int N)
{
    int t = threadIdx.x;
    int i = blockIdx.x * 256 + t;
    int v = (i < N) ? g_deg[i] : 0;
#pragma unroll
    for (int o = 16; o; o >>= 1) v += __shfl_down_sync(~0u, v, o);
    __shared__ int ws[8];
    if ((t & 31) == 0) ws[t >> 5] = v;
    __syncthreads();
    if (t == 0) {
        int s = 0;
#pragma unroll
        for (int k = 0; k < 8; k++) s += ws[k];
        g_bsum[blockIdx.x] = s;
    }
}

__global__ void k_bscan(int nb)
{
    __shared__ int sm[256];
    int t = threadIdx.x;
    int v = (t < nb) ? g_bsum[t] : 0;
    sm[t] = v;
    __syncthreads();
    for (int o = 1; o < 256; o <<= 1) {
        int a = (t >= o) ? sm[t - o] : 0;
        __syncthreads();
        sm[t] += a;
        __syncthreads();
    }
    g_bpre[t] = sm[t] - v;
}

__global__ void k_off(int N)
{
    int t = threadIdx.x;
    int i = blockIdx.x * 256 + t;
    int v = (i < N) ? g_deg[i] : 0;
    int lane = t & 31, wid = t >> 5;
    int x = v;
#pragma unroll
    for (int o = 1; o < 32; o <<= 1) {
        int y = __shfl_up_sync(~0u, x, o);
        if (lane >= o) x += y;
    }
    __shared__ int ws[8];
    if (lane == 31) ws[wid] = x;
    __syncthreads();
    if (t < 8) {
        int y = ws[t];
#pragma unroll
        for (int o = 1; o < 8; o <<= 1) {
            int z = __shfl_up_sync(0xff, y, o);
            if (t >= o) y += z;
        }
        ws[t] = y;
    }
    __syncthreads();
    int incl = x + (wid ? ws[wid - 1] : 0);
    int off = g_bpre[blockIdx.x] + incl - v;
    if (i < N) { g_off[i] = off; g_cur[i] = off; }
    if (i == N - 1) g_off[N] = off + v;
}

__global__ void k_fill(int E)
{
    int i = blockIdx.x * blockDim.x + threadIdx.x;
    if (i < E) {
        int d = g_dstv[i];
        int p = atomicAdd(&g_cur[d], 1);
        g_nbr[p] = g_src[i];
    }
}

// ---------------- GIN aggregation: out[i] = x[i] + sum_{j in N(i)} x[j] ----------------
__global__ void k_gather128(const float* __restrict__ xin, float* __restrict__ out, int N)
{
    if (blockIdx.x == 0) { g_colsum[threadIdx.x] = 0.f; g_colsq[threadIdx.x] = 0.f; }
    int gt = blockIdx.x * blockDim.x + threadIdx.x;
    int w = gt >> 5, lane = gt & 31;
    if (w >= N) return;
    const float4* xp = (const float4*)xin;
    float4 a = xp[(size_t)w * 32 + lane];
    int e = g_off[w], e1 = g_off[w + 1];
    for (; e + 1 < e1; e += 2) {
        int n0 = g_nbr[e], n1 = g_nbr[e + 1];
        float4 v0 = xp[(size_t)n0 * 32 + lane];
        float4 v1 = xp[(size_t)n1 * 32 + lane];
        a.x += v0.x; a.y += v0.y; a.z += v0.z; a.w += v0.w;
        a.x += v1.x; a.y += v1.y; a.z += v1.z; a.w += v1.w;
    }
    if (e < e1) {
        float4 v = xp[(size_t)g_nbr[e] * 32 + lane];
        a.x += v.x; a.y += v.y; a.z += v.z; a.w += v.w;
    }
    ((float4*)out)[(size_t)w * 32 + lane] = a;
}

__global__ void k_gather256(const float* __restrict__ xin, float* __restrict__ out, int N)
{
    if (blockIdx.x == 0) { g_colsum[threadIdx.x] = 0.f; g_colsq[threadIdx.x] = 0.f; }
    int gt = blockIdx.x * blockDim.x + threadIdx.x;
    int w = gt >> 5, lane = gt & 31;
    if (w >= N) return;
    const float4* xp = (const float4*)xin;
    float4 a0 = xp[(size_t)w * 64 + lane];
    float4 a1 = xp[(size_t)w * 64 + 32 + lane];
    int e = g_off[w], e1 = g_off[w + 1];
    for (; e + 1 < e1; e += 2) {
        size_t b0 = (size_t)g_nbr[e] * 64;
        size_t b1 = (size_t)g_nbr[e + 1] * 64;
        float4 u0 = xp[b0 + lane];
        float4 u1 = xp[b0 + 32 + lane];
        float4 w0 = xp[b1 + lane];
        float4 w1 = xp[b1 + 32 + lane];
        a0.x += u0.x; a0.y += u0.y; a0.z += u0.z; a0.w += u0.w;
        a1.x += u1.x; a1.y += u1.y; a1.z += u1.z; a1.w += u1.w;
        a0.x += w0.x; a0.y += w0.y; a0.z += w0.z; a0.w += w0.w;
        a1.x += w1.x; a1.y += w1.y; a1.z += w1.z; a1.w += w1.w;
    }
    if (e < e1) {
        size_t b = (size_t)g_nbr[e] * 64;
        float4 v0 = xp[b + lane];
        float4 v1 = xp[b + 32 + lane];
        a0.x += v0.x; a0.y += v0.y; a0.z += v0.z; a0.w += v0.w;
        a1.x += v1.x; a1.y += v1.y; a1.z += v1.z; a1.w += v1.w;
    }
    ((float4*)out)[(size_t)w * 64 + lane]      = a0;
    ((float4*)out)[(size_t)w * 64 + 32 + lane] = a1;
}

// ---------------- tf32 tensor-core GEMM ----------------
__device__ __forceinline__ uint32_t f2tf(float x)
{
    uint32_t u;
    asm("cvt.rna.tf32.f32 %0, %1;" : "=r"(u) : "f"(x));
    return u;
}

#define MMA_TF32(d, a, b)                                                    \
    asm volatile("mma.sync.aligned.m16n8k8.row.col.f32.tf32.tf32.f32 "      \
                 "{%0,%1,%2,%3}, {%4,%5,%6,%7}, {%8,%9}, {%0,%1,%2,%3};"    \
                 : "+f"(d[0]), "+f"(d[1]), "+f"(d[2]), "+f"(d[3])            \
                 : "r"(a[0]), "r"(a[1]), "r"(a[2]), "r"(a[3]),               \
                   "r"(b[0]), "r"(b[1]))

// H = A[M,K] @ W[K,256] + bias, fused per-column sum/sumsq for BN.
// 256 thr = 8 warps in 2(M)x4(N); warp tile 64x32 = 4x4 m16n8k8 tiles.
template <int K>
__launch_bounds__(256, 2)
__global__ void k_gemm(const float* __restrict__ A, const float* __restrict__ W,
                       const float* __restrict__ bias, float* __restrict__ Hout, int M)
{
    const int BM = 128, BN = 128, BK = 16;
    __shared__ uint32_t As[BM][20];    // stride 20 -> conflict-free A-frag LDS
    __shared__ uint32_t Bs[BK][136];   // stride 136 -> conflict-free B-frag LDS
    __shared__ float RedS[BN], RedQ[BN];

    int bm = blockIdx.x * BM, bn = blockIdx.y * BN;
    int t = threadIdx.x, lane = t & 31, w = t >> 5;
    int m_warp = (w & 1) * 64;
    int n_warp = (w >> 1) * 32;

    float acc[4][4][4];
#pragma unroll
    for (int mt = 0; mt < 4; mt++)
#pragma unroll
        for (int nt = 0; nt < 4; nt++)
#pragma unroll
            for (int f = 0; f < 4; f++) acc[mt][nt][f] = 0.f;

    int arow = t >> 1;          // 0..127
    int acol = (t & 1) * 8;     // 0 / 8
    int brow = t >> 4;          // 0..15
    int bcol = (t & 15) * 8;    // 0..120

    for (int k0 = 0; k0 < K; k0 += BK) {
        // stage A (zero-fill tail rows), cvt to tf32
        {
            float4 v0 = make_float4(0.f, 0.f, 0.f, 0.f), v1 = v0;
            int gr = bm + arow;
            if (gr < M) {
                const float* ap = A + (size_t)gr * K + k0 + acol;
                v0 = *(const float4*)ap;
                v1 = *(const float4*)(ap + 4);
            }
            uint4 t0 = make_uint4(f2tf(v0.x), f2tf(v0.y), f2tf(v0.z), f2tf(v0.w));
            uint4 t1 = make_uint4(f2tf(v1.x), f2tf(v1.y), f2tf(v1.z), f2tf(v1.w));
            *(uint4*)&As[arow][acol]     = t0;
            *(uint4*)&As[arow][acol + 4] = t1;
        }
        // stage B
        {
            const float* bp = W + (size_t)(k0 + brow) * HD + bn + bcol;
            float4 u0 = *(const float4*)bp;
            float4 u1 = *(const float4*)(bp + 4);
            uint4 t0 = make_uint4(f2tf(u0.x), f2tf(u0.y), f2tf(u0.z), f2tf(u0.w));
            uint4 t1 = make_uint4(f2tf(u1.x), f2tf(u1.y), f2tf(u1.z), f2tf(u1.w));
            *(uint4*)&Bs[brow][bcol]     = t0;
            *(uint4*)&Bs[brow][bcol + 4] = t1;
        }
        __syncthreads();

#pragma unroll
        for (int kk = 0; kk < BK; kk += 8) {
            uint32_t af[4][4], bf[4][2];
            int ar = lane >> 2, ac = lane & 3;
#pragma unroll
            for (int mt = 0; mt < 4; mt++) {
                int r = m_warp + mt * 16 + ar;
                af[mt][0] = As[r][kk + ac];
                af[mt][1] = As[r + 8][kk + ac];
                af[mt][2] = As[r][kk + ac + 4];
                af[mt][3] = As[r + 8][kk + ac + 4];
            }
            int br = lane & 3, bc = lane >> 2;
#pragma unroll
            for (int nt = 0; nt < 4; nt++) {
                int c = n_warp + nt * 8 + bc;
                bf[nt][0] = Bs[kk + br][c];
                bf[nt][1] = Bs[kk + br + 4][c];
            }
#pragma unroll
            for (int mt = 0; mt < 4; mt++)
#pragma unroll
                for (int nt = 0; nt < 4; nt++)
                    MMA_TF32(acc[mt][nt], af[mt], bf[nt]);
        }
        __syncthreads();
    }

    // ---- epilogue: bias, store, per-column sum/sumsq ----
    if (t < BN) { RedS[t] = 0.f; RedQ[t] = 0.f; }
    __syncthreads();

    int ar = lane >> 2;
    int ac2 = (lane & 3) * 2;
#pragma unroll
    for (int nt = 0; nt < 4; nt++) {
        int cc = n_warp + nt * 8 + ac2;         // local col (even)
        float b0 = bias[bn + cc], b1 = bias[bn + cc + 1];
        float s0 = 0.f, q0 = 0.f, s1 = 0.f, q1 = 0.f;
#pragma unroll
        for (int mt = 0; mt < 4; mt++) {
            int gr0 = bm + m_warp + mt * 16 + ar;
            int gr1 = gr0 + 8;
            if (gr0 < M) {
                float o0 = acc[mt][nt][0] + b0;
                float o1 = acc[mt][nt][1] + b1;
                *(float2*)(Hout + (size_t)gr0 * HD + bn + cc) = make_float2(o0, o1);
                s0 += o0; q0 += o0 * o0; s1 += o1; q1 += o1 * o1;
            }
            if (gr1 < M) {
                float o2 = acc[mt][nt][2] + b0;
                float o3 = acc[mt][nt][3] + b1;
                *(float2*)(Hout + (size_t)gr1 * HD + bn + cc) = make_float2(o2, o3);
                s0 += o2; q0 += o2 * o2; s1 += o3; q1 += o3 * o3;
            }
        }
        atomicAdd(&RedS[cc], s0);
        atomicAdd(&RedQ[cc], q0);
        atomicAdd(&RedS[cc + 1], s1);
        atomicAdd(&RedQ[cc + 1], q1);
    }
    __syncthreads();
    if (t < BN) {
        atomicAdd(&g_colsum[bn + t], RedS[t]);
        atomicAdd(&g_colsq[bn + t],  RedQ[t]);
    }
}

// ---------------- BN (train-mode, biased var) + ReLU (+ residual) ----------------
__global__ void k_bnrelu(const float* __restrict__ Hin, const float* __restrict__ gam,
                         const float* __restrict__ bet, const float* __restrict__ resid,
                         float* __restrict__ out, int M)
{
    size_t idx = (size_t)blockIdx.x * blockDim.x + threadIdx.x;
    size_t tot = (size_t)M * (HD / 4);
    if (idx >= tot) return;
    int c4 = (int)(idx & 63);
    float invN = 1.0f / (float)M;
    float4 h = ((const float4*)Hin)[idx];
    float hv[4] = { h.x, h.y, h.z, h.w };
    float o[4];
#pragma unroll
    for (int j = 0; j < 4; j++) {
        int c = c4 * 4 + j;
        float m = g_colsum[c] * invN;
        float v = fmaf(-m, m, g_colsq[c] * invN);
        float sc = gam[c] * rsqrtf(v + 1e-5f);
        float sh = fmaf(-m, sc, bet[c]);
        o[j] = fmaxf(fmaf(hv[j], sc, sh), 0.0f);
    }
    if (resid) {
        float4 rr = ((const float4*)resid)[idx];
        o[0] += rr.x; o[1] += rr.y; o[2] += rr.z; o[3] += rr.w;
    }
    ((float4*)out)[idx] = make_float4(o[0], o[1], o[2], o[3]);
}

// ---------------- pool: batch sorted -> register-accumulate, flush on change ----------------
__global__ void k_pool2(const float* __restrict__ x3, int N)
{
    __shared__ int sb[128];
    int n0 = blockIdx.x * 128;
    int n1 = n0 + 128; if (n1 > N) n1 = N;
    int t = threadIdx.x;
    if (t < n1 - n0) sb[t] = g_batch[n0 + t];
    __syncthreads();
    if (n1 <= n0) return;
    float acc = 0.f;
    int curg = sb[0], cnt = 0;
    for (int n = n0; n < n1; n++) {
        int g = sb[n - n0];
        if (g != curg) {
            atomicAdd(&g_pool[curg * HD + t], acc);
            if (t == 0) atomicAdd(&g_cnt[curg], (float)cnt);
            acc = 0.f; cnt = 0; curg = g;
        }
        acc += x3[(size_t)n * HD + t];
        cnt++;
    }
    atomicAdd(&g_pool[curg * HD + t], acc);
    if (t == 0) atomicAdd(&g_cnt[curg], (float)cnt);
}

// ---------------- final MLP head (64 graphs) ----------------
__global__ void k_final(const float* __restrict__ fcW1, const float* __restrict__ fcb1,
                        const float* __restrict__ fcW2, const float* __restrict__ fcb2,
                        float* __restrict__ out)
{
    __shared__ float prow[HD];
    __shared__ float hred[HD];
    int g = blockIdx.x, t = threadIdx.x;
    float cnt = fmaxf(g_cnt[g], 1.0f);
    prow[t] = g_pool[g * HD + t] / cnt;
    __syncthreads();
    float acc = fcb1[t];
    for (int k = 0; k < HD; k++)
        acc = fmaf(prow[k], __ldg(fcW1 + (size_t)k * HD + t), acc);
    float h = fmaxf(acc, 0.0f);
    hred[t] = h * fcW2[t];
    __syncthreads();
    for (int s = HD / 2; s > 0; s >>= 1) {
        if (t < s) hred[t] += hred[t + s];
        __syncthreads();
    }
    if (t == 0) out[g] = hred[0] + fcb2[0];
}

// ---------------- launch ----------------
extern "C" void kernel_launch(void* const* d_in, const int* in_sizes, int n_in,
                              void* d_out, int out_size)
{
    int base = 3;
    if (n_in >= 20 && in_sizes[3] == 1) base = 4;

    const float* x   = (const float*)d_in[0];
    const int*   ei  = (const int*)d_in[1];
    const int*   bat = (const int*)d_in[2];
    const float* W1  = (const float*)d_in[base + 0];
    const float* b1  = (const float*)d_in[base + 1];
    const float* W2  = (const float*)d_in[base + 2];
    const float* b2  = (const float*)d_in[base + 3];
    const float* W3  = (const float*)d_in[base + 4];
    const float* b3  = (const float*)d_in[base + 5];
    const float* ga1 = (const float*)d_in[base + 6];
    const float* be1 = (const float*)d_in[base + 7];
    const float* ga2 = (const float*)d_in[base + 8];
    const float* be2 = (const float*)d_in[base + 9];
    const float* ga3 = (const float*)d_in[base + 10];
    const float* be3 = (const float*)d_in[base + 11];
    const float* fcW1 = (const float*)d_in[base + 12];
    const float* fcb1 = (const float*)d_in[base + 13];
    const float* fcW2 = (const float*)d_in[base + 14];
    const float* fcb2 = (const float*)d_in[base + 15];

    int N = in_sizes[0] / 128;
    int E = in_sizes[1] / 2;

    void* p;
    float *agg, *hbuf, *xa, *xb;
    cudaGetSymbolAddress(&p, g_agg);  agg  = (float*)p;
    cudaGetSymbolAddress(&p, g_hbuf); hbuf = (float*)p;
    cudaGetSymbolAddress(&p, g_xa);   xa   = (float*)p;
    cudaGetSymbolAddress(&p, g_xb);   xb   = (float*)p;
    void *ppool, *pcnt;
    cudaGetSymbolAddress(&ppool, g_pool);
    cudaGetSymbolAddress(&pcnt,  g_cnt);

    const int tb = 256;
    int ebl = (E + tb - 1) / tb;
    int nb256 = (N + 255) / 256;
    int wbl = (N * 32 + tb - 1) / tb;
    int bnbl = (int)(((size_t)N * (HD / 4) + tb - 1) / tb);
    dim3 ggrid((N + 127) / 128, 2);

    // index normalization + CSR (shared by all 3 layers)
    k_detect<<<1, 32>>>(ei, bat, N);
    k_convert<<<ebl, tb>>>(ei, bat, E, N);
    k_count<<<ebl, tb>>>(E);
    k_bsum<<<nb256, 256>>>(N);
    k_bscan<<<1, 256>>>(nb256);
    k_off<<<nb256, 256>>>(N);
    k_fill<<<ebl, tb>>>(E);

    // layer 1: K=128
    k_gather128<<<wbl, tb>>>(x, agg, N);
    k_gemm<128><<<ggrid, 256>>>(agg, W1, b1, hbuf, N);
    k_bnrelu<<<bnbl, tb>>>(hbuf, ga1, be1, nullptr, xa, N);

    // layer 2
    k_gather256<<<wbl, tb>>>(xa, agg, N);
    k_gemm<256><<<ggrid, 256>>>(agg, W2, b2, hbuf, N);
    k_bnrelu<<<bnbl, tb>>>(hbuf, ga2, be2, xa, xb, N);

    // layer 3
    k_gather256<<<wbl, tb>>>(xb, agg, N);
    k_gemm<256><<<ggrid, 256>>>(agg, W3, b3, hbuf, N);
    k_bnrelu<<<bnbl, tb>>>(hbuf, ga3, be3, xb, xa, N);

    // pool + head
    cudaMemsetAsync(ppool, 0, NGR * HD * sizeof(float));
    cudaMemsetAsync(pcnt, 0, NGR * sizeof(float));
    k_pool2<<<(N + 127) / 128, 256>>>(xa, N);
    k_final<<<NGR, 256>>>(fcW1, fcb1, fcW2, fcb2, (float*)d_out);
}

// round 4
// speedup vs baseline: 2.5352x; 1.0151x over previous
#include <cuda_runtime.h>
#include <cuda_fp16.h>
#include <stdint.h>

#define HD 256
#define NMAX 50048
#define EMAX 800000
#define NGR 64

// ---------------- device scratch (static, no runtime alloc) ----------------
__device__ float  g_agg [(size_t)NMAX * HD];
__device__ float  g_hbuf[(size_t)NMAX * HD];
__device__ __half g_x16 [(size_t)NMAX * 128];
__device__ __half g_xah [(size_t)NMAX * HD];
__device__ __half g_xbh [(size_t)NMAX * HD];
__device__ int    g_src [EMAX];
__device__ int    g_dstv[EMAX];
__device__ int    g_nbr [EMAX];
__device__ int    g_deg [NMAX];
__device__ int    g_off [NMAX + 1];
__device__ int    g_cur [NMAX];
__device__ int    g_batch[NMAX];
__device__ int    g_bsum[1024];
__device__ int    g_bpre[1024];
__device__ float  g_colsum[HD];
__device__ float  g_colsq [HD];
__device__ float  g_pool[NGR * HD];
__device__ float  g_cnt [NGR];
__device__ int    g_flags[2];

// ---------------- cp.async helpers ----------------
__device__ __forceinline__ void cp16(void* smem, const void* g, int sz)
{
    uint32_t s = (uint32_t)__cvta_generic_to_shared(smem);
    asm volatile("cp.async.cg.shared.global [%0], [%1], 16, %2;" :: "r"(s), "l"(g), "r"(sz));
}
#define CP_COMMIT() asm volatile("cp.async.commit_group;")
#define CP_WAIT1()  asm volatile("cp.async.wait_group 1;")
#define CP_WAIT0()  asm volatile("cp.async.wait_group 0;")

// ---------------- dtype sniffing + index normalization ----------------
__global__ void k_detect(const int* __restrict__ ei, const int* __restrict__ bat, int N)
{
    if (threadIdx.x == 0 && blockIdx.x == 0) {
        int e64 = (ei[1] == 0 && ei[3] == 0 && ei[5] == 0 && ei[7] == 0) ? 1 : 0;
        int w = N - 1; if (!(w & 1)) w--;
        int b64 = (bat[w] == 0) ? 1 : 0;
        g_flags[0] = e64;
        g_flags[1] = b64;
    }
}

// convert + fused degree count (g_deg pre-zeroed by memset)
__global__ void k_convert(const int* __restrict__ ei, const int* __restrict__ bat, int E, int N)
{
    int i = blockIdx.x * blockDim.x + threadIdx.x;
    int e64 = g_flags[0], b64 = g_flags[1];
    if (i < E) {
        int s, d;
        if (e64) { s = ei[2 * i]; d = ei[2 * (E + i)]; }
        else     { s = ei[i];     d = ei[E + i]; }
        g_src[i] = s; g_dstv[i] = d;
        atomicAdd(&g_deg[d], 1);
    }
    if (i < N) g_batch[i] = b64 ? bat[2 * i] : bat[i];
}

__global__ void k_bsum(int N)
{
    int t = threadIdx.x;
    int i = blockIdx.x * 256 + t;
    int v = (i < N) ? g_deg[i] : 0;
#pragma unroll
    for (int o = 16; o; o >>= 1) v += __shfl_down_sync(~0u, v, o);
    __shared__ int ws[8];
    if ((t & 31) == 0) ws[t >> 5] = v;
    __syncthreads();
    if (t == 0) {
        int s = 0;
#pragma unroll
        for (int k = 0; k < 8; k++) s += ws[k];
        g_bsum[blockIdx.x] = s;
    }
}

__global__ void k_bscan(int nb)
{
    __shared__ int sm[256];
    int t = threadIdx.x;
    int v = (t < nb) ? g_bsum[t] : 0;
    sm[t] = v;
    __syncthreads();
    for (int o = 1; o < 256; o <<= 1) {
        int a = (t >= o) ? sm[t - o] : 0;
        __syncthreads();
        sm[t] += a;
        __syncthreads();
    }
    g_bpre[t] = sm[t] - v;
}

__global__ void k_off(int N)
{
    int t = threadIdx.x;
    int i = blockIdx.x * 256 + t;
    int v = (i < N) ? g_deg[i] : 0;
    int lane = t & 31, wid = t >> 5;
    int x = v;
#pragma unroll
    for (int o = 1; o < 32; o <<= 1) {
        int y = __shfl_up_sync(~0u, x, o);
        if (lane >= o) x += y;
    }
    __shared__ int ws[8];
    if (lane == 31) ws[wid] = x;
    __syncthreads();
    if (t < 8) {
        int y = ws[t];
#pragma unroll
        for (int o = 1; o < 8; o <<= 1) {
            int z = __shfl_up_sync(0xff, y, o);
            if (t >= o) y += z;
        }
        ws[t] = y;
    }
    __syncthreads();
    int incl = x + (wid ? ws[wid - 1] : 0);
    int off = g_bpre[blockIdx.x] + incl - v;
    if (i < N) { g_off[i] = off; g_cur[i] = off; }
    if (i == N - 1) g_off[N] = off + v;
}

__global__ void k_fill(int E)
{
    int i = blockIdx.x * blockDim.x + threadIdx.x;
    if (i < E) {
        int d = g_dstv[i];
        int p = atomicAdd(&g_cur[d], 1);
        g_nbr[p] = g_src[i];
    }
}

// ---------------- fp32 x -> fp16 copy (layer-1 gather input) ----------------
__global__ void k_x2h(const float* __restrict__ x, int total4)
{
    int i = blockIdx.x * blockDim.x + threadIdx.x;   // 4 elems each
    if (i >= total4) return;
    float4 v = ((const float4*)x)[i];
    __half2* o = (__half2*)g_x16;
    o[2 * i]     = __floats2half2_rn(v.x, v.y);
    o[2 * i + 1] = __floats2half2_rn(v.z, v.w);
}

// ---------------- GIN aggregation (fp16 in, fp32 out): out[i] = x[i] + sum_j x[j] ----------------
__global__ void k_gather128h(float* __restrict__ out, int N)
{
    if (blockIdx.x == 0) { g_colsum[threadIdx.x] = 0.f; g_colsq[threadIdx.x] = 0.f; }
    int gt = blockIdx.x * blockDim.x + threadIdx.x;
    int w = gt >> 5, lane = gt & 31;
    if (w >= N) return;
    const uint2* xp = (const uint2*)g_x16;          // row = 32 uint2 (128 halves)
    float acc[4] = {0.f, 0.f, 0.f, 0.f};
    {
        uint2 s = xp[(size_t)w * 32 + lane];
        float2 a = __half22float2(*(const __half2*)&s.x);
        float2 b = __half22float2(*(const __half2*)&s.y);
        acc[0] += a.x; acc[1] += a.y; acc[2] += b.x; acc[3] += b.y;
    }
    int e = g_off[w], e1 = g_off[w + 1];
    for (; e < e1; e++) {
        uint2 s = xp[(size_t)g_nbr[e] * 32 + lane];
        float2 a = __half22float2(*(const __half2*)&s.x);
        float2 b = __half22float2(*(const __half2*)&s.y);
        acc[0] += a.x; acc[1] += a.y; acc[2] += b.x; acc[3] += b.y;
    }
    ((float4*)out)[(size_t)w * 32 + lane] = make_float4(acc[0], acc[1], acc[2], acc[3]);
}

__global__ void k_gather256h(const __half* __restrict__ xin, float* __restrict__ out, int N)
{
    if (blockIdx.x == 0) { g_colsum[threadIdx.x] = 0.f; g_colsq[threadIdx.x] = 0.f; }
    int gt = blockIdx.x * blockDim.x + threadIdx.x;
    int w = gt >> 5, lane = gt & 31;
    if (w >= N) return;
    const uint4* xp = (const uint4*)xin;            // row = 32 uint4 (256 halves)
    float acc[8];
    {
        uint4 s = xp[(size_t)w * 32 + lane];
        float2 a = __half22float2(*(const __half2*)&s.x);
        float2 b = __half22float2(*(const __half2*)&s.y);
        float2 c = __half22float2(*(const __half2*)&s.z);
        float2 d = __half22float2(*(const __half2*)&s.w);
        acc[0] = a.x; acc[1] = a.y; acc[2] = b.x; acc[3] = b.y;
        acc[4] = c.x; acc[5] = c.y; acc[6] = d.x; acc[7] = d.y;
    }
    int e = g_off[w], e1 = g_off[w + 1];
    for (; e < e1; e++) {
        uint4 s = xp[(size_t)g_nbr[e] * 32 + lane];
        float2 a = __half22float2(*(const __half2*)&s.x);
        float2 b = __half22float2(*(const __half2*)&s.y);
        float2 c = __half22float2(*(const __half2*)&s.z);
        float2 d = __half22float2(*(const __half2*)&s.w);
        acc[0] += a.x; acc[1] += a.y; acc[2] += b.x; acc[3] += b.y;
        acc[4] += c.x; acc[5] += c.y; acc[6] += d.x; acc[7] += d.y;
    }
    float4* op = (float4*)out;
    op[(size_t)w * 64 + lane * 2]     = make_float4(acc[0], acc[1], acc[2], acc[3]);
    op[(size_t)w * 64 + lane * 2 + 1] = make_float4(acc[4], acc[5], acc[6], acc[7]);
}

// ---------------- tf32 tensor-core GEMM, cp.async double-buffered ----------------
#define MMA_TF32(d, a, b)                                                    \
    asm volatile("mma.sync.aligned.m16n8k8.row.col.f32.tf32.tf32.f32 "      \
                 "{%0,%1,%2,%3}, {%4,%5,%6,%7}, {%8,%9}, {%0,%1,%2,%3};"    \
                 : "+f"(d[0]), "+f"(d[1]), "+f"(d[2]), "+f"(d[3])            \
                 : "r"(a[0]), "r"(a[1]), "r"(a[2]), "r"(a[3]),               \
                   "r"(b[0]), "r"(b[1]))

template <int K>
__launch_bounds__(256, 2)
__global__ void k_gemm(const float* __restrict__ A, const float* __restrict__ W,
                       const float* __restrict__ bias, float* __restrict__ Hout, int M)
{
    const int BM = 128, BN = 128, BK = 16;
    const int NIT = K / BK;
    __shared__ float As[2][BM][20];
    __shared__ float Bs[2][BK][136];
    __shared__ float RedS[BN], RedQ[BN];

    int bm = blockIdx.x * BM, bn = blockIdx.y * BN;
    int t = threadIdx.x, lane = t & 31, w = t >> 5;
    int m_warp = (w & 1) * 64;
    int n_warp = (w >> 1) * 32;

    int arow = t >> 1;          // 0..127
    int acol = (t & 1) * 8;     // 0 / 8
    int brow = t >> 4;          // 0..15
    int bcol = (t & 15) * 8;    // 0..120
    int gr_a = bm + arow;
    int asz = (gr_a < M) ? 16 : 0;
    const float* apB = A + (size_t)gr_a * K + acol;
    const float* bpB = W + (size_t)brow * HD + bn + bcol;

    float acc[4][4][4];
#pragma unroll
    for (int mt = 0; mt < 4; mt++)
#pragma unroll
        for (int nt = 0; nt < 4; nt++)
#pragma unroll
            for (int f = 0; f < 4; f++) acc[mt][nt][f] = 0.f;

    // stage k-tile 0
    {
        cp16(&As[0][arow][acol],     apB,     asz);
        cp16(&As[0][arow][acol + 4], apB + 4, asz);
        cp16(&Bs[0][brow][bcol],     bpB,     16);
        cp16(&Bs[0][brow][bcol + 4], bpB + 4, 16);
        CP_COMMIT();
    }

    for (int it = 0; it < NIT; it++) {
        int buf = it & 1;
        if (it + 1 < NIT) {
            int k0 = (it + 1) * BK;
            cp16(&As[buf ^ 1][arow][acol],     apB + k0,     asz);
            cp16(&As[buf ^ 1][arow][acol + 4], apB + k0 + 4, asz);
            cp16(&Bs[buf ^ 1][brow][bcol],     bpB + (size_t)k0 * HD,     16);
            cp16(&Bs[buf ^ 1][brow][bcol + 4], bpB + (size_t)k0 * HD + 4, 16);
            CP_COMMIT();
            CP_WAIT1();
        } else {
            CP_WAIT0();
        }
        __syncthreads();

#pragma unroll
        for (int kk = 0; kk < BK; kk += 8) {
            uint32_t af[4][4], bf[4][2];
            int ar = lane >> 2, ac = lane & 3;
#pragma unroll
            for (int mt = 0; mt < 4; mt++) {
                int r = m_warp + mt * 16 + ar;
                af[mt][0] = __float_as_uint(As[buf][r][kk + ac]);
                af[mt][1] = __float_as_uint(As[buf][r + 8][kk + ac]);
                af[mt][2] = __float_as_uint(As[buf][r][kk + ac + 4]);
                af[mt][3] = __float_as_uint(As[buf][r + 8][kk + ac + 4]);
            }
            int br = lane & 3, bc = lane >> 2;
#pragma unroll
            for (int nt = 0; nt < 4; nt++) {
                int c = n_warp + nt * 8 + bc;
                bf[nt][0] = __float_as_uint(Bs[buf][kk + br][c]);
                bf[nt][1] = __float_as_uint(Bs[buf][kk + br + 4][c]);
            }
#pragma unroll
            for (int mt = 0; mt < 4; mt++)
#pragma unroll
                for (int nt = 0; nt < 4; nt++)
                    MMA_TF32(acc[mt][nt], af[mt], bf[nt]);
        }
        __syncthreads();
    }

    // ---- epilogue: bias, store, per-column sum/sumsq ----
    if (t < BN) { RedS[t] = 0.f; RedQ[t] = 0.f; }
    __syncthreads();

    int ar = lane >> 2;
    int ac2 = (lane & 3) * 2;
#pragma unroll
    for (int nt = 0; nt < 4; nt++) {
        int cc = n_warp + nt * 8 + ac2;
        float b0 = bias[bn + cc], b1 = bias[bn + cc + 1];
        float s0 = 0.f, q0 = 0.f, s1 = 0.f, q1 = 0.f;
#pragma unroll
        for (int mt = 0; mt < 4; mt++) {
            int gr0 = bm + m_warp + mt * 16 + ar;
            int gr1 = gr0 + 8;
            if (gr0 < M) {
                float o0 = acc[mt][nt][0] + b0;
                float o1 = acc[mt][nt][1] + b1;
                *(float2*)(Hout + (size_t)gr0 * HD + bn + cc) = make_float2(o0, o1);
                s0 += o0; q0 += o0 * o0; s1 += o1; q1 += o1 * o1;
            }
            if (gr1 < M) {
                float o2 = acc[mt][nt][2] + b0;
                float o3 = acc[mt][nt][3] + b1;
                *(float2*)(Hout + (size_t)gr1 * HD + bn + cc) = make_float2(o2, o3);
                s0 += o2; q0 += o2 * o2; s1 += o3; q1 += o3 * o3;
            }
        }
        atomicAdd(&RedS[cc], s0);
        atomicAdd(&RedQ[cc], q0);
        atomicAdd(&RedS[cc + 1], s1);
        atomicAdd(&RedQ[cc + 1], q1);
    }
    __syncthreads();
    if (t < BN) {
        atomicAdd(&g_colsum[bn + t], RedS[t]);
        atomicAdd(&g_colsq[bn + t],  RedQ[t]);
    }
}

// ---------------- BN + ReLU (+ fp16 residual), fp16 output ----------------
__global__ void k_bnrelu_h(const float* __restrict__ Hin, const float* __restrict__ gam,
                           const float* __restrict__ bet, const __half* __restrict__ resid,
                           __half* __restrict__ out, int M)
{
    int idx = blockIdx.x * blockDim.x + threadIdx.x;   // 8 elems each
    if (idx >= M * 32) return;
    int c8 = (idx & 31) * 8;
    float invN = 1.0f / (float)M;
    float4 h0 = ((const float4*)Hin)[idx * 2];
    float4 h1 = ((const float4*)Hin)[idx * 2 + 1];
    float hv[8] = { h0.x, h0.y, h0.z, h0.w, h1.x, h1.y, h1.z, h1.w };
    float o[8];
#pragma unroll
    for (int j = 0; j < 8; j++) {
        int c = c8 + j;
        float m = g_colsum[c] * invN;
        float v = fmaf(-m, m, g_colsq[c] * invN);
        float sc = gam[c] * rsqrtf(v + 1e-5f);
        float sh = fmaf(-m, sc, bet[c]);
        o[j] = fmaxf(fmaf(hv[j], sc, sh), 0.0f);
    }
    if (resid) {
        uint4 r = ((const uint4*)resid)[idx];
        float2 r0 = __half22float2(*(const __half2*)&r.x);
        float2 r1 = __half22float2(*(const __half2*)&r.y);
        float2 r2 = __half22float2(*(const __half2*)&r.z);
        float2 r3 = __half22float2(*(const __half2*)&r.w);
        o[0] += r0.x; o[1] += r0.y; o[2] += r1.x; o[3] += r1.y;
        o[4] += r2.x; o[5] += r2.y; o[6] += r3.x; o[7] += r3.y;
    }
    __half2 p0 = __floats2half2_rn(o[0], o[1]);
    __half2 p1 = __floats2half2_rn(o[2], o[3]);
    __half2 p2 = __floats2half2_rn(o[4], o[5]);
    __half2 p3 = __floats2half2_rn(o[6], o[7]);
    uint4 pk;
    pk.x = *(uint32_t*)&p0; pk.y = *(uint32_t*)&p1;
    pk.z = *(uint32_t*)&p2; pk.w = *(uint32_t*)&p3;
    ((uint4*)out)[idx] = pk;
}

// ---------------- pool: batch sorted -> register-accumulate, flush on change ----------------
__global__ void k_pool2(const __half* __restrict__ x3, int N)
{
    __shared__ int sb[128];
    int n0 = blockIdx.x * 128;
    int n1 = n0 + 128; if (n1 > N) n1 = N;
    int t = threadIdx.x;
    if (t < n1 - n0) sb[t] = g_batch[n0 + t];
    __syncthreads();
    if (n1 <= n0) return;
    float acc = 0.f;
    int curg = sb[0], cnt = 0;
    for (int n = n0; n < n1; n++) {
        int g = sb[n - n0];
        if (g != curg) {
            atomicAdd(&g_pool[curg * HD + t], acc);
            if (t == 0) atomicAdd(&g_cnt[curg], (float)cnt);
            acc = 0.f; cnt = 0; curg = g;
        }
        acc += __half2float(x3[(size_t)n * HD + t]);
        cnt++;
    }
    atomicAdd(&g_pool[curg * HD + t], acc);
    if (t == 0) atomicAdd(&g_cnt[curg], (float)cnt);
}

// ---------------- final MLP head (64 graphs) ----------------
__global__ void k_final(const float* __restrict__ fcW1, const float* __restrict__ fcb1,
                        const float* __restrict__ fcW2, const float* __restrict__ fcb2,
                        float* __restrict__ out)
{
    __shared__ float prow[HD];
    __shared__ float hred[HD];
    int g = blockIdx.x, t = threadIdx.x;
    float cnt = fmaxf(g_cnt[g], 1.0f);
    prow[t] = g_pool[g * HD + t] / cnt;
    __syncthreads();
    float acc = fcb1[t];
    for (int k = 0; k < HD; k++)
        acc = fmaf(prow[k], __ldg(fcW1 + (size_t)k * HD + t), acc);
    float h = fmaxf(acc, 0.0f);
    hred[t] = h * fcW2[t];
    __syncthreads();
    for (int s = HD / 2; s > 0; s >>= 1) {
        if (t < s) hred[t] += hred[t + s];
        __syncthreads();
    }
    if (t == 0) out[g] = hred[0] + fcb2[0];
}

// ---------------- launch ----------------
extern "C" void kernel_launch(void* const* d_in, const int* in_sizes, int n_in,
                              void* d_out, int out_size)
{
    int base = 3;
    if (n_in >= 20 && in_sizes[3] == 1) base = 4;

    const float* x   = (const float*)d_in[0];
    const int*   ei  = (const int*)d_in[1];
    const int*   bat = (const int*)d_in[2];
    const float* W1  = (const float*)d_in[base + 0];
    const float* b1  = (const float*)d_in[base + 1];
    const float* W2  = (const float*)d_in[base + 2];
    const float* b2  = (const float*)d_in[base + 3];
    const float* W3  = (const float*)d_in[base + 4];
    const float* b3  = (const float*)d_in[base + 5];
    const float* ga1 = (const float*)d_in[base + 6];
    const float* be1 = (const float*)d_in[base + 7];
    const float* ga2 = (const float*)d_in[base + 8];
    const float* be2 = (const float*)d_in[base + 9];
    const float* ga3 = (const float*)d_in[base + 10];
    const float* be3 = (const float*)d_in[base + 11];
    const float* fcW1 = (const float*)d_in[base + 12];
    const float* fcb1 = (const float*)d_in[base + 13];
    const float* fcW2 = (const float*)d_in[base + 14];
    const float* fcb2 = (const float*)d_in[base + 15];

    int N = in_sizes[0] / 128;
    int E = in_sizes[1] / 2;

    void* p;
    float *agg, *hbuf;
    __half *xah, *xbh;
    cudaGetSymbolAddress(&p, g_agg);  agg  = (float*)p;
    cudaGetSymbolAddress(&p, g_hbuf); hbuf = (float*)p;
    cudaGetSymbolAddress(&p, g_xah);  xah  = (__half*)p;
    cudaGetSymbolAddress(&p, g_xbh);  xbh  = (__half*)p;
    void *pdeg, *ppool, *pcnt;
    cudaGetSymbolAddress(&pdeg,  g_deg);
    cudaGetSymbolAddress(&ppool, g_pool);
    cudaGetSymbolAddress(&pcnt,  g_cnt);

    const int tb = 256;
    int ebl = (E + tb - 1) / tb;
    int nb256 = (N + 255) / 256;
    int wbl = (N * 32 + tb - 1) / tb;
    int bnbl = (N * 32 + tb - 1) / tb;
    dim3 ggrid((N + 127) / 128, 2);

    // index normalization + CSR (shared by all 3 layers)
    k_detect<<<1, 32>>>(ei, bat, N);
    cudaMemsetAsync(pdeg, 0, (size_t)N * sizeof(int));
    k_convert<<<ebl, tb>>>(ei, bat, E, N);
    k_bsum<<<nb256, 256>>>(N);
    k_bscan<<<1, 256>>>(nb256);
    k_off<<<nb256, 256>>>(N);
    k_fill<<<ebl, tb>>>(E);

    // layer 1: K=128 (fp16 copy of x, then gather)
    k_x2h<<<(N * 32 + tb - 1) / tb, tb>>>(x, N * 32);
    k_gather128h<<<wbl, tb>>>(agg, N);
    k_gemm<128><<<ggrid, 256>>>(agg, W1, b1, hbuf, N);
    k_bnrelu_h<<<bnbl, tb>>>(hbuf, ga1, be1, nullptr, xah, N);

    // layer 2
    k_gather256h<<<wbl, tb>>>(xah, agg, N);
    k_gemm<256><<<ggrid, 256>>>(agg, W2, b2, hbuf, N);
    k_bnrelu_h<<<bnbl, tb>>>(hbuf, ga2, be2, xah, xbh, N);

    // layer 3
    k_gather256h<<<wbl, tb>>>(xbh, agg, N);
    k_gemm<256><<<ggrid, 256>>>(agg, W3, b3, hbuf, N);
    k_bnrelu_h<<<bnbl, tb>>>(hbuf, ga3, be3, xbh, xah, N);

    // pool + head
    cudaMemsetAsync(ppool, 0, NGR * HD * sizeof(float));
    cudaMemsetAsync(pcnt, 0, NGR * sizeof(float));
    k_pool2<<<(N + 127) / 128, 256>>>(xah, N);
    k_final<<<NGR, 256>>>(fcW1, fcb1, fcW2, fcb2, (float*)d_out);
}

// round 5
// speedup vs baseline: 2.8494x; 1.1239x over previous
#include <cuda_runtime.h>
#include <cuda_fp16.h>
#include <stdint.h>

#define HD 256
#define NMAX 50048
#define EMAX 800000
#define NGR 64

// ---------------- device scratch (static, no runtime alloc) ----------------
__device__ __half g_aggh[(size_t)NMAX * HD];
__device__ float  g_hbuf[(size_t)NMAX * HD];
__device__ __half g_x16 [(size_t)NMAX * 128];
__device__ __half g_xah [(size_t)NMAX * HD];
__device__ __half g_xbh [(size_t)NMAX * HD];
__device__ __half g_w1t [128 * 256];          // [n][k] fp16 transposed
__device__ __half g_w2t [256 * 256];
__device__ __half g_w3t [256 * 256];
__device__ int    g_src [EMAX];
__device__ int    g_dstv[EMAX];
__device__ int    g_nbr [EMAX];
__device__ int    g_deg [NMAX];
__device__ int    g_off [NMAX + 1];
__device__ int    g_cur [NMAX];
__device__ int    g_batch[NMAX];
__device__ int    g_bsum[1024];
__device__ int    g_bpre[1024];
__device__ float  g_colsum[HD];
__device__ float  g_colsq [HD];
__device__ float  g_pool[NGR * HD];
__device__ float  g_cnt [NGR];
__device__ int    g_flags[2];

// ---------------- cp.async helpers ----------------
__device__ __forceinline__ void cp16(void* smem, const void* g, int sz)
{
    uint32_t s = (uint32_t)__cvta_generic_to_shared(smem);
    asm volatile("cp.async.cg.shared.global [%0], [%1], 16, %2;" :: "r"(s), "l"(g), "r"(sz));
}
#define CP_COMMIT() asm volatile("cp.async.commit_group;")
#define CP_WAIT1()  asm volatile("cp.async.wait_group 1;")
#define CP_WAIT0()  asm volatile("cp.async.wait_group 0;")

// ---------------- dtype sniffing + index normalization ----------------
__global__ void k_detect(const int* __restrict__ ei, const int* __restrict__ bat, int N)
{
    if (threadIdx.x == 0 && blockIdx.x == 0) {
        int e64 = (ei[1] == 0 && ei[3] == 0 && ei[5] == 0 && ei[7] == 0) ? 1 : 0;
        int w = N - 1; if (!(w & 1)) w--;
        int b64 = (bat[w] == 0) ? 1 : 0;
        g_flags[0] = e64;
        g_flags[1] = b64;
    }
}

// convert + fused degree count (g_deg pre-zeroed by memset)
__global__ void k_convert(const int* __restrict__ ei, const int* __restrict__ bat, int E, int N)
{
    int i = blockIdx.x * blockDim.x + threadIdx.x;
    int e64 = g_flags[0], b64 = g_flags[1];
    if (i < E) {
        int s, d;
        if (e64) { s = ei[2 * i]; d = ei[2 * (E + i)]; }
        else     { s = ei[i];     d = ei[E + i]; }
        g_src[i] = s; g_dstv[i] = d;
        atomicAdd(&g_deg[d], 1);
    }
    if (i < N) g_batch[i] = b64 ? bat[2 * i] : bat[i];
}

__global__ void k_bsum(int N)
{
    int t = threadIdx.x;
    int i = blockIdx.x * 256 + t;
    int v = (i < N) ? g_deg[i] : 0;
#pragma unroll
    for (int o = 16; o; o >>= 1) v += __shfl_down_sync(~0u, v, o);
    __shared__ int ws[8];
    if ((t & 31) == 0) ws[t >> 5] = v;
    __syncthreads();
    if (t == 0) {
        int s = 0;
#pragma unroll
        for (int k = 0; k < 8; k++) s += ws[k];
        g_bsum[blockIdx.x] = s;
    }
}

__global__ void k_bscan(int nb)
{
    __shared__ int sm[256];
    int t = threadIdx.x;
    int v = (t < nb) ? g_bsum[t] : 0;
    sm[t] = v;
    __syncthreads();
    for (int o = 1; o < 256; o <<= 1) {
        int a = (t >= o) ? sm[t - o] : 0;
        __syncthreads();
        sm[t] += a;
        __syncthreads();
    }
    g_bpre[t] = sm[t] - v;
}

__global__ void k_off(int N)
{
    int t = threadIdx.x;
    int i = blockIdx.x * 256 + t;
    int v = (i < N) ? g_deg[i] : 0;
    int lane = t & 31, wid = t >> 5;
    int x = v;
#pragma unroll
    for (int o = 1; o < 32; o <<= 1) {
        int y = __shfl_up_sync(~0u, x, o);
        if (lane >= o) x += y;
    }
    __shared__ int ws[8];
    if (lane == 31) ws[wid] = x;
    __syncthreads();
    if (t < 8) {
        int y = ws[t];
#pragma unroll
        for (int o = 1; o < 8; o <<= 1) {
            int z = __shfl_up_sync(0xff, y, o);
            if (t >= o) y += z;
        }
        ws[t] = y;
    }
    __syncthreads();
    int incl = x + (wid ? ws[wid - 1] : 0);
    int off = g_bpre[blockIdx.x] + incl - v;
    if (i < N) { g_off[i] = off; g_cur[i] = off; }
    if (i == N - 1) g_off[N] = off + v;
}

__global__ void k_fill(int E)
{
    int i = blockIdx.x * blockDim.x + threadIdx.x;
    if (i < E) {
        int d = g_dstv[i];
        int p = atomicAdd(&g_cur[d], 1);
        g_nbr[p] = g_src[i];
    }
}

// ---------------- fp32 x -> fp16 copy (layer-1 gather input) ----------------
__global__ void k_x2h(const float* __restrict__ x, int total4)
{
    int i = blockIdx.x * blockDim.x + threadIdx.x;   // 4 elems each
    if (i >= total4) return;
    float4 v = ((const float4*)x)[i];
    __half2* o = (__half2*)g_x16;
    o[2 * i]     = __floats2half2_rn(v.x, v.y);
    o[2 * i + 1] = __floats2half2_rn(v.z, v.w);
}

// ---------------- weight convert + transpose: Wt[n][k] = W[k][n] (fp16) ----------------
__global__ void k_w2h(const float* __restrict__ W, __half* __restrict__ Wt, int K)
{
    int n = blockIdx.x;           // 0..255
    for (int k = threadIdx.x; k < K; k += blockDim.x)
        Wt[(size_t)n * K + k] = __float2half(W[(size_t)k * HD + n]);
}

// ---------------- GIN aggregation (fp16 in/out, fp32 accum) ----------------
__global__ void k_gather128h(__half* __restrict__ out, int N)
{
    if (blockIdx.x == 0) { g_colsum[threadIdx.x] = 0.f; g_colsq[threadIdx.x] = 0.f; }
    int gt = blockIdx.x * blockDim.x + threadIdx.x;
    int w = gt >> 5, lane = gt & 31;
    if (w >= N) return;
    const uint2* xp = (const uint2*)g_x16;          // row = 32 uint2 (128 halves)
    float acc[4];
    {
        uint2 s = xp[(size_t)w * 32 + lane];
        float2 a = __half22float2(*(const __half2*)&s.x);
        float2 b = __half22float2(*(const __half2*)&s.y);
        acc[0] = a.x; acc[1] = a.y; acc[2] = b.x; acc[3] = b.y;
    }
    int e = g_off[w], e1 = g_off[w + 1];
    for (; e + 1 < e1; e += 2) {
        uint2 s0 = xp[(size_t)g_nbr[e] * 32 + lane];
        uint2 s1 = xp[(size_t)g_nbr[e + 1] * 32 + lane];
        float2 a0 = __half22float2(*(const __half2*)&s0.x);
        float2 b0 = __half22float2(*(const __half2*)&s0.y);
        float2 a1 = __half22float2(*(const __half2*)&s1.x);
        float2 b1 = __half22float2(*(const __half2*)&s1.y);
        acc[0] += a0.x + a1.x; acc[1] += a0.y + a1.y;
        acc[2] += b0.x + b1.x; acc[3] += b0.y + b1.y;
    }
    if (e < e1) {
        uint2 s = xp[(size_t)g_nbr[e] * 32 + lane];
        float2 a = __half22float2(*(const __half2*)&s.x);
        float2 b = __half22float2(*(const __half2*)&s.y);
        acc[0] += a.x; acc[1] += a.y; acc[2] += b.x; acc[3] += b.y;
    }
    __half2 p0 = __floats2half2_rn(acc[0], acc[1]);
    __half2 p1 = __floats2half2_rn(acc[2], acc[3]);
    uint2 pk; pk.x = *(uint32_t*)&p0; pk.y = *(uint32_t*)&p1;
    ((uint2*)out)[(size_t)w * 32 + lane] = pk;
}

__global__ void k_gather256h(const __half* __restrict__ xin, __half* __restrict__ out, int N)
{
    if (blockIdx.x == 0) { g_colsum[threadIdx.x] = 0.f; g_colsq[threadIdx.x] = 0.f; }
    int gt = blockIdx.x * blockDim.x + threadIdx.x;
    int w = gt >> 5, lane = gt & 31;
    if (w >= N) return;
    const uint4* xp = (const uint4*)xin;            // row = 32 uint4 (256 halves)
    float acc[8];
    {
        uint4 s = xp[(size_t)w * 32 + lane];
        float2 a = __half22float2(*(const __half2*)&s.x);
        float2 b = __half22float2(*(const __half2*)&s.y);
        float2 c = __half22float2(*(const __half2*)&s.z);
        float2 d = __half22float2(*(const __half2*)&s.w);
        acc[0] = a.x; acc[1] = a.y; acc[2] = b.x; acc[3] = b.y;
        acc[4] = c.x; acc[5] = c.y; acc[6] = d.x; acc[7] = d.y;
    }
    int e = g_off[w], e1 = g_off[w + 1];
    for (; e + 1 < e1; e += 2) {
        uint4 s0 = xp[(size_t)g_nbr[e] * 32 + lane];
        uint4 s1 = xp[(size_t)g_nbr[e + 1] * 32 + lane];
        float2 a0 = __half22float2(*(const __half2*)&s0.x);
        float2 b0 = __half22float2(*(const __half2*)&s0.y);
        float2 c0 = __half22float2(*(const __half2*)&s0.z);
        float2 d0 = __half22float2(*(const __half2*)&s0.w);
        float2 a1 = __half22float2(*(const __half2*)&s1.x);
        float2 b1 = __half22float2(*(const __half2*)&s1.y);
        float2 c1 = __half22float2(*(const __half2*)&s1.z);
        float2 d1 = __half22float2(*(const __half2*)&s1.w);
        acc[0] += a0.x + a1.x; acc[1] += a0.y + a1.y;
        acc[2] += b0.x + b1.x; acc[3] += b0.y + b1.y;
        acc[4] += c0.x + c1.x; acc[5] += c0.y + c1.y;
        acc[6] += d0.x + d1.x; acc[7] += d0.y + d1.y;
    }
    if (e < e1) {
        uint4 s = xp[(size_t)g_nbr[e] * 32 + lane];
        float2 a = __half22float2(*(const __half2*)&s.x);
        float2 b = __half22float2(*(const __half2*)&s.y);
        float2 c = __half22float2(*(const __half2*)&s.z);
        float2 d = __half22float2(*(const __half2*)&s.w);
        acc[0] += a.x; acc[1] += a.y; acc[2] += b.x; acc[3] += b.y;
        acc[4] += c.x; acc[5] += c.y; acc[6] += d.x; acc[7] += d.y;
    }
    __half2 p0 = __floats2half2_rn(acc[0], acc[1]);
    __half2 p1 = __floats2half2_rn(acc[2], acc[3]);
    __half2 p2 = __floats2half2_rn(acc[4], acc[5]);
    __half2 p3 = __floats2half2_rn(acc[6], acc[7]);
    uint4 pk;
    pk.x = *(uint32_t*)&p0; pk.y = *(uint32_t*)&p1;
    pk.z = *(uint32_t*)&p2; pk.w = *(uint32_t*)&p3;
    ((uint4*)out)[(size_t)w * 32 + lane] = pk;
}

// ---------------- fp16 tensor-core GEMM (m16n8k16, fp32 accum) ----------------
#define MMA_F16(d, a, b)                                                          \
    asm volatile("mma.sync.aligned.m16n8k16.row.col.f32.f16.f16.f32 "            \
                 "{%0,%1,%2,%3}, {%4,%5,%6,%7}, {%8,%9}, {%0,%1,%2,%3};"         \
                 : "+f"(d[0]), "+f"(d[1]), "+f"(d[2]), "+f"(d[3])                 \
                 : "r"(a[0]), "r"(a[1]), "r"(a[2]), "r"(a[3]),                    \
                   "r"(b[0]), "r"(b[1]))

// H[M,256] = A[M,K](fp16) @ Wt[256,K]^T(fp16) + bias; fused col sum/sumsq.
// 256 thr = 8 warps 2(M)x4(N); warp 64x32 = 4x4 m16n8k16 tiles; BK=32, cp.async 2-buf.
template <int K>
__launch_bounds__(256, 2)
__global__ void k_gemm(const __half* __restrict__ A, const __half* __restrict__ Wt,
                       const float* __restrict__ bias, float* __restrict__ Hout, int M)
{
    const int BM = 128, BN = 128, BK = 32;
    const int NIT = K / BK;
    const int LDA = 40;                       // halves; banks (r*20+c)%32 distinct
    __shared__ __half As[2][BM][LDA];
    __shared__ __half Bs[2][BN][LDA];
    __shared__ float RedS[BN], RedQ[BN];

    int bm = blockIdx.x * BM, bn = blockIdx.y * BN;
    int t = threadIdx.x, lane = t & 31, w = t >> 5;
    int m_warp = (w & 1) * 64;
    int n_warp = (w >> 1) * 32;

    // staging map: 512 x 16B transfers per matrix-tile; thread does u=t and u=t+256
    int r0 = t >> 2, s0 = (t & 3) * 8;                 // rows 0..63
    int r1 = (t + 256) >> 2, s1 = s0;                  // rows 64..127
    int gA0 = bm + r0, gA1 = bm + r1;
    int az0 = (gA0 < M) ? 16 : 0, az1 = (gA1 < M) ? 16 : 0;
    const __half* apB0 = A + (size_t)gA0 * K + s0;
    const __half* apB1 = A + (size_t)gA1 * K + s1;
    const __half* bpB0 = Wt + (size_t)(bn + r0) * K + s0;
    const __half* bpB1 = Wt + (size_t)(bn + r1) * K + s1;

    float acc[4][4][4];
#pragma unroll
    for (int mt = 0; mt < 4; mt++)
#pragma unroll
        for (int nt = 0; nt < 4; nt++)
#pragma unroll
            for (int f = 0; f < 4; f++) acc[mt][nt][f] = 0.f;

    // stage tile 0
    cp16(&As[0][r0][s0], apB0, az0);
    cp16(&As[0][r1][s1], apB1, az1);
    cp16(&Bs[0][r0][s0], bpB0, 16);
    cp16(&Bs[0][r1][s1], bpB1, 16);
    CP_COMMIT();

    for (int it = 0; it < NIT; it++) {
        int buf = it & 1;
        if (it + 1 < NIT) {
            int k0 = (it + 1) * BK;
            cp16(&As[buf ^ 1][r0][s0], apB0 + k0, az0);
            cp16(&As[buf ^ 1][r1][s1], apB1 + k0, az1);
            cp16(&Bs[buf ^ 1][r0][s0], bpB0 + k0, 16);
            cp16(&Bs[buf ^ 1][r1][s1], bpB1 + k0, 16);
            CP_COMMIT();
            CP_WAIT1();
        } else {
            CP_WAIT0();
        }
        __syncthreads();

        int ar = lane >> 2, ac = (lane & 3) * 2;
#pragma unroll
        for (int ks = 0; ks < 2; ks++) {
            int kk = ks * 16;
            uint32_t af[4][4], bf[4][2];
#pragma unroll
            for (int mt = 0; mt < 4; mt++) {
                int r = m_warp + mt * 16 + ar;
                af[mt][0] = *(const uint32_t*)&As[buf][r][kk + ac];
                af[mt][1] = *(const uint32_t*)&As[buf][r + 8][kk + ac];
                af[mt][2] = *(const uint32_t*)&As[buf][r][kk + ac + 8];
                af[mt][3] = *(const uint32_t*)&As[buf][r + 8][kk + ac + 8];
            }
#pragma unroll
            for (int nt = 0; nt < 4; nt++) {
                int c = n_warp + nt * 8 + ar;
                bf[nt][0] = *(const uint32_t*)&Bs[buf][c][kk + ac];
                bf[nt][1] = *(const uint32_t*)&Bs[buf][c][kk + ac + 8];
            }
#pragma unroll
            for (int mt = 0; mt < 4; mt++)
#pragma unroll
                for (int nt = 0; nt < 4; nt++)
                    MMA_F16(acc[mt][nt], af[mt], bf[nt]);
        }
        __syncthreads();
    }

    // ---- epilogue: bias, store, per-column sum/sumsq ----
    if (t < BN) { RedS[t] = 0.f; RedQ[t] = 0.f; }
    __syncthreads();

    int ar = lane >> 2;
    int ac2 = (lane & 3) * 2;
#pragma unroll
    for (int nt = 0; nt < 4; nt++) {
        int cc = n_warp + nt * 8 + ac2;
        float b0 = bias[bn + cc], b1 = bias[bn + cc + 1];
        float s0a = 0.f, q0 = 0.f, s1a = 0.f, q1 = 0.f;
#pragma unroll
        for (int mt = 0; mt < 4; mt++) {
            int gr0 = bm + m_warp + mt * 16 + ar;
            int gr1 = gr0 + 8;
            if (gr0 < M) {
                float o0 = acc[mt][nt][0] + b0;
                float o1 = acc[mt][nt][1] + b1;
                *(float2*)(Hout + (size_t)gr0 * HD + bn + cc) = make_float2(o0, o1);
                s0a += o0; q0 += o0 * o0; s1a += o1; q1 += o1 * o1;
            }
            if (gr1 < M) {
                float o2 = acc[mt][nt][2] + b0;
                float o3 = acc[mt][nt][3] + b1;
                *(float2*)(Hout + (size_t)gr1 * HD + bn + cc) = make_float2(o2, o3);
                s0a += o2; q0 += o2 * o2; s1a += o3; q1 += o3 * o3;
            }
        }
        atomicAdd(&RedS[cc], s0a);
        atomicAdd(&RedQ[cc], q0);
        atomicAdd(&RedS[cc + 1], s1a);
        atomicAdd(&RedQ[cc + 1], q1);
    }
    __syncthreads();
    if (t < BN) {
        atomicAdd(&g_colsum[bn + t], RedS[t]);
        atomicAdd(&g_colsq[bn + t],  RedQ[t]);
    }
}

// ---------------- BN + ReLU (+ fp16 residual), fp16 output ----------------
__global__ void k_bnrelu_h(const float* __restrict__ Hin, const float* __restrict__ gam,
                           const float* __restrict__ bet, const __half* __restrict__ resid,
                           __half* __restrict__ out, int M)
{
    int idx = blockIdx.x * blockDim.x + threadIdx.x;   // 8 elems each
    if (idx >= M * 32) return;
    int c8 = (idx & 31) * 8;
    float invN = 1.0f / (float)M;
    float4 h0 = ((const float4*)Hin)[idx * 2];
    float4 h1 = ((const float4*)Hin)[idx * 2 + 1];
    float hv[8] = { h0.x, h0.y, h0.z, h0.w, h1.x, h1.y, h1.z, h1.w };
    float o[8];
#pragma unroll
    for (int j = 0; j < 8; j++) {
        int c = c8 + j;
        float m = g_colsum[c] * invN;
        float v = fmaf(-m, m, g_colsq[c] * invN);
        float sc = gam[c] * rsqrtf(v + 1e-5f);
        float sh = fmaf(-m, sc, bet[c]);
        o[j] = fmaxf(fmaf(hv[j], sc, sh), 0.0f);
    }
    if (resid) {
        uint4 r = ((const uint4*)resid)[idx];
        float2 r0 = __half22float2(*(const __half2*)&r.x);
        float2 r1 = __half22float2(*(const __half2*)&r.y);
        float2 r2 = __half22float2(*(const __half2*)&r.z);
        float2 r3 = __half22float2(*(const __half2*)&r.w);
        o[0] += r0.x; o[1] += r0.y; o[2] += r1.x; o[3] += r1.y;
        o[4] += r2.x; o[5] += r2.y; o[6] += r3.x; o[7] += r3.y;
    }
    __half2 p0 = __floats2half2_rn(o[0], o[1]);
    __half2 p1 = __floats2half2_rn(o[2], o[3]);
    __half2 p2 = __floats2half2_rn(o[4], o[5]);
    __half2 p3 = __floats2half2_rn(o[6], o[7]);
    uint4 pk;
    pk.x = *(uint32_t*)&p0; pk.y = *(uint32_t*)&p1;
    pk.z = *(uint32_t*)&p2; pk.w = *(uint32_t*)&p3;
    ((uint4*)out)[idx] = pk;
}

// ---------------- pool: batch sorted -> register-accumulate, flush on change ----------------
__global__ void k_pool2(const __half* __restrict__ x3, int N)
{
    __shared__ int sb[128];
    int n0 = blockIdx.x * 128;
    int n1 = n0 + 128; if (n1 > N) n1 = N;
    int t = threadIdx.x;
    if (t < n1 - n0) sb[t] = g_batch[n0 + t];
    __syncthreads();
    if (n1 <= n0) return;
    float acc = 0.f;
    int curg = sb[0], cnt = 0;
    for (int n = n0; n < n1; n++) {
        int g = sb[n - n0];
        if (g != curg) {
            atomicAdd(&g_pool[curg * HD + t], acc);
            if (t == 0) atomicAdd(&g_cnt[curg], (float)cnt);
            acc = 0.f; cnt = 0; curg = g;
        }
        acc += __half2float(x3[(size_t)n * HD + t]);
        cnt++;
    }
    atomicAdd(&g_pool[curg * HD + t], acc);
    if (t == 0) atomicAdd(&g_cnt[curg], (float)cnt);
}

// ---------------- final MLP head (64 graphs) ----------------
__global__ void k_final(const float* __restrict__ fcW1, const float* __restrict__ fcb1,
                        const float* __restrict__ fcW2, const float* __restrict__ fcb2,
                        float* __restrict__ out)
{
    __shared__ float prow[HD];
    __shared__ float hred[HD];
    int g = blockIdx.x, t = threadIdx.x;
    float cnt = fmaxf(g_cnt[g], 1.0f);
    prow[t] = g_pool[g * HD + t] / cnt;
    __syncthreads();
    float acc = fcb1[t];
    for (int k = 0; k < HD; k++)
        acc = fmaf(prow[k], __ldg(fcW1 + (size_t)k * HD + t), acc);
    float h = fmaxf(acc, 0.0f);
    hred[t] = h * fcW2[t];
    __syncthreads();
    for (int s = HD / 2; s > 0; s >>= 1) {
        if (t < s) hred[t] += hred[t + s];
        __syncthreads();
    }
    if (t == 0) out[g] = hred[0] + fcb2[0];
}

// ---------------- launch ----------------
extern "C" void kernel_launch(void* const* d_in, const int* in_sizes, int n_in,
                              void* d_out, int out_size)
{
    int base = 3;
    if (n_in >= 20 && in_sizes[3] == 1) base = 4;

    const float* x   = (const float*)d_in[0];
    const int*   ei  = (const int*)d_in[1];
    const int*   bat = (const int*)d_in[2];
    const float* W1  = (const float*)d_in[base + 0];
    const float* b1  = (const float*)d_in[base + 1];
    const float* W2  = (const float*)d_in[base + 2];
    const float* b2  = (const float*)d_in[base + 3];
    const float* W3  = (const float*)d_in[base + 4];
    const float* b3  = (const float*)d_in[base + 5];
    const float* ga1 = (const float*)d_in[base + 6];
    const float* be1 = (const float*)d_in[base + 7];
    const float* ga2 = (const float*)d_in[base + 8];
    const float* be2 = (const float*)d_in[base + 9];
    const float* ga3 = (const float*)d_in[base + 10];
    const float* be3 = (const float*)d_in[base + 11];
    const float* fcW1 = (const float*)d_in[base + 12];
    const float* fcb1 = (const float*)d_in[base + 13];
    const float* fcW2 = (const float*)d_in[base + 14];
    const float* fcb2 = (const float*)d_in[base + 15];

    int N = in_sizes[0] / 128;
    int E = in_sizes[1] / 2;

    void* p;
    __half *aggh, *xah, *xbh, *w1t, *w2t, *w3t;
    float* hbuf;
    cudaGetSymbolAddress(&p, g_aggh); aggh = (__half*)p;
    cudaGetSymbolAddress(&p, g_hbuf); hbuf = (float*)p;
    cudaGetSymbolAddress(&p, g_xah);  xah  = (__half*)p;
    cudaGetSymbolAddress(&p, g_xbh);  xbh  = (__half*)p;
    cudaGetSymbolAddress(&p, g_w1t);  w1t  = (__half*)p;
    cudaGetSymbolAddress(&p, g_w2t);  w2t  = (__half*)p;
    cudaGetSymbolAddress(&p, g_w3t);  w3t  = (__half*)p;
    void *pdeg, *ppool, *pcnt;
    cudaGetSymbolAddress(&pdeg,  g_deg);
    cudaGetSymbolAddress(&ppool, g_pool);
    cudaGetSymbolAddress(&pcnt,  g_cnt);

    const int tb = 256;
    int ebl = (E + tb - 1) / tb;
    int nb256 = (N + 255) / 256;
    int wbl = (N * 32 + tb - 1) / tb;
    int bnbl = (N * 32 + tb - 1) / tb;
    dim3 ggrid((N + 127) / 128, 2);

    // index normalization + CSR + weight prep
    k_detect<<<1, 32>>>(ei, bat, N);
    cudaMemsetAsync(pdeg, 0, (size_t)N * sizeof(int));
    k_convert<<<ebl, tb>>>(ei, bat, E, N);
    k_w2h<<<256, 128>>>(W1, w1t, 128);
    k_w2h<<<256, 128>>>(W2, w2t, 256);
    k_w2h<<<256, 128>>>(W3, w3t, 256);
    k_bsum<<<nb256, 256>>>(N);
    k_bscan<<<1, 256>>>(nb256);
    k_off<<<nb256, 256>>>(N);
    k_fill<<<ebl, tb>>>(E);

    // layer 1: K=128 (fp16 copy of x, then gather)
    k_x2h<<<(N * 32 + tb - 1) / tb, tb>>>(x, N * 32);
    k_gather128h<<<wbl, tb>>>(aggh, N);
    k_gemm<128><<<ggrid, 256>>>(aggh, w1t, b1, hbuf, N);
    k_bnrelu_h<<<bnbl, tb>>>(hbuf, ga1, be1, nullptr, xah, N);

    // layer 2
    k_gather256h<<<wbl, tb>>>(xah, aggh, N);
    k_gemm<256><<<ggrid, 256>>>(aggh, w2t, b2, hbuf, N);
    k_bnrelu_h<<<bnbl, tb>>>(hbuf, ga2, be2, xah, xbh, N);

    // layer 3
    k_gather256h<<<wbl, tb>>>(xbh, aggh, N);
    k_gemm<256><<<ggrid, 256>>>(aggh, w3t, b3, hbuf, N);
    k_bnrelu_h<<<bnbl, tb>>>(hbuf, ga3, be3, xbh, xah, N);

    // pool + head
    cudaMemsetAsync(ppool, 0, NGR * HD * sizeof(float));
    cudaMemsetAsync(pcnt, 0, NGR * sizeof(float));
    k_pool2<<<(N + 127) / 128, 256>>>(xah, N);
    k_final<<<NGR, 256>>>(fcW1, fcb1, fcW2, fcb2, (float*)d_out);
}

// round 6
// speedup vs baseline: 3.0594x; 1.0737x over previous
#include <cuda_runtime.h>
#include <cuda_fp16.h>
#include <stdint.h>

#define HD 256
#define NMAX 50048
#define EMAX 800000
#define NGR 64

// ---------------- device scratch (static, no runtime alloc) ----------------
__device__ __half g_aggh[(size_t)NMAX * HD];
__device__ float  g_hbuf[(size_t)NMAX * HD];   // used as fp16 (capacity 2x)
__device__ __half g_x16 [(size_t)NMAX * 128];
__device__ __half g_xah [(size_t)NMAX * HD];
__device__ __half g_xbh [(size_t)NMAX * HD];
__device__ __half g_w1t [128 * 256];           // [n][k] fp16 transposed
__device__ __half g_w2t [256 * 256];
__device__ __half g_w3t [256 * 256];
__device__ int    g_src [EMAX];
__device__ int    g_dstv[EMAX];
__device__ int    g_nbr [EMAX];
__device__ int    g_deg [NMAX];
__device__ int    g_off [NMAX + 1];
__device__ int    g_cur [NMAX];
__device__ int    g_batch[NMAX];
__device__ int    g_bsum[1024];
__device__ int    g_bpre[1024];
__device__ float  g_colsum[HD];
__device__ float  g_colsq [HD];
__device__ float  g_pool[NGR * HD];
__device__ float  g_cnt [NGR];

// ---------------- cp.async helpers ----------------
__device__ __forceinline__ void cp16(void* smem, const void* g, int sz)
{
    uint32_t s = (uint32_t)__cvta_generic_to_shared(smem);
    asm volatile("cp.async.cg.shared.global [%0], [%1], 16, %2;" :: "r"(s), "l"(g), "r"(sz));
}
#define CP_COMMIT() asm volatile("cp.async.commit_group;")
#define CP_WAIT1()  asm volatile("cp.async.wait_group 1;")
#define CP_WAIT0()  asm volatile("cp.async.wait_group 0;")

#define LDSM_X4(r0, r1, r2, r3, addr)                                        \
    asm volatile("ldmatrix.sync.aligned.m8n8.x4.shared.b16 {%0,%1,%2,%3}, [%4];" \
                 : "=r"(r0), "=r"(r1), "=r"(r2), "=r"(r3) : "r"(addr))

// ---------------- convert (inline dtype detect) + degree count ----------------
__global__ void k_convert(const int* __restrict__ ei, const int* __restrict__ bat, int E, int N)
{
    int e64 = (ei[1] == 0 && ei[3] == 0 && ei[5] == 0 && ei[7] == 0) ? 1 : 0;
    int w = N - 1; if (!(w & 1)) w--;
    int b64 = (bat[w] == 0) ? 1 : 0;
    int i = blockIdx.x * blockDim.x + threadIdx.x;
    if (i < E) {
        int s, d;
        if (e64) { s = ei[2 * i]; d = ei[2 * (E + i)]; }
        else     { s = ei[i];     d = ei[E + i]; }
        g_src[i] = s; g_dstv[i] = d;
        atomicAdd(&g_deg[d], 1);
    }
    if (i < N) g_batch[i] = b64 ? bat[2 * i] : bat[i];
}

// ---------------- prep: x->fp16 copy + 3 weight transposes, one kernel ----------------
__global__ void k_prep(const float* __restrict__ x, const float* __restrict__ W1,
                       const float* __restrict__ W2, const float* __restrict__ W3,
                       int N, int nx)
{
    int b = blockIdx.x, t = threadIdx.x;
    if (b < nx) {                          // x2h: 4 floats per thread
        int i = b * 256 + t;
        if (i < N * 32) {
            float4 v = ((const float4*)x)[i];
            __half2* o = (__half2*)g_x16;
            o[2 * i]     = __floats2half2_rn(v.x, v.y);
            o[2 * i + 1] = __floats2half2_rn(v.z, v.w);
        }
    } else {
        int wb = b - nx;                   // 0..767
        const float* W = (wb < 256) ? W1 : ((wb < 512) ? W2 : W3);
        __half* Wt = (wb < 256) ? g_w1t : ((wb < 512) ? g_w2t : g_w3t);
        int K = (wb < 256) ? 128 : 256;
        int n = wb & 255;
        for (int k = t; k < K; k += 256)
            Wt[(size_t)n * K + k] = __float2half(W[(size_t)k * HD + n]);
    }
}

// ---------------- CSR scan pipeline ----------------
__global__ void k_bsum(int N)
{
    int t = threadIdx.x;
    int i = blockIdx.x * 256 + t;
    int v = (i < N) ? g_deg[i] : 0;
#pragma unroll
    for (int o = 16; o; o >>= 1) v += __shfl_down_sync(~0u, v, o);
    __shared__ int ws[8];
    if ((t & 31) == 0) ws[t >> 5] = v;
    __syncthreads();
    if (t == 0) {
        int s = 0;
#pragma unroll
        for (int k = 0; k < 8; k++) s += ws[k];
        g_bsum[blockIdx.x] = s;
    }
}

__global__ void k_bscan(int nb)
{
    __shared__ int sm[256];
    int t = threadIdx.x;
    int v = (t < nb) ? g_bsum[t] : 0;
    sm[t] = v;
    __syncthreads();
    for (int o = 1; o < 256; o <<= 1) {
        int a = (t >= o) ? sm[t - o] : 0;
        __syncthreads();
        sm[t] += a;
        __syncthreads();
    }
    g_bpre[t] = sm[t] - v;
}

__global__ void k_off(int N)
{
    int t = threadIdx.x;
    int i = blockIdx.x * 256 + t;
    int v = (i < N) ? g_deg[i] : 0;
    int lane = t & 31, wid = t >> 5;
    int x = v;
#pragma unroll
    for (int o = 1; o < 32; o <<= 1) {
        int y = __shfl_up_sync(~0u, x, o);
        if (lane >= o) x += y;
    }
    __shared__ int ws[8];
    if (lane == 31) ws[wid] = x;
    __syncthreads();
    if (t < 8) {
        int y = ws[t];
#pragma unroll
        for (int o = 1; o < 8; o <<= 1) {
            int z = __shfl_up_sync(0xff, y, o);
            if (t >= o) y += z;
        }
        ws[t] = y;
    }
    __syncthreads();
    int incl = x + (wid ? ws[wid - 1] : 0);
    int off = g_bpre[blockIdx.x] + incl - v;
    if (i < N) { g_off[i] = off; g_cur[i] = off; }
    if (i == N - 1) g_off[N] = off + v;
}

__global__ void k_fill(int E)
{
    int i = blockIdx.x * blockDim.x + threadIdx.x;
    if (i < E) {
        int d = g_dstv[i];
        int p = atomicAdd(&g_cur[d], 1);
        g_nbr[p] = g_src[i];
    }
}

// ---------------- GIN aggregation (fp16 in/out, fp32 accum) ----------------
__global__ void k_gather128h(__half* __restrict__ out, int N)
{
    if (blockIdx.x == 0) { g_colsum[threadIdx.x] = 0.f; g_colsq[threadIdx.x] = 0.f; }
    int gt = blockIdx.x * blockDim.x + threadIdx.x;
    int w = gt >> 5, lane = gt & 31;
    if (w >= N) return;
    const uint2* xp = (const uint2*)g_x16;
    float acc[4];
    {
        uint2 s = xp[(size_t)w * 32 + lane];
        float2 a = __half22float2(*(const __half2*)&s.x);
        float2 b = __half22float2(*(const __half2*)&s.y);
        acc[0] = a.x; acc[1] = a.y; acc[2] = b.x; acc[3] = b.y;
    }
    int e = g_off[w], e1 = g_off[w + 1];
    for (; e + 1 < e1; e += 2) {
        uint2 s0 = xp[(size_t)g_nbr[e] * 32 + lane];
        uint2 s1 = xp[(size_t)g_nbr[e + 1] * 32 + lane];
        float2 a0 = __half22float2(*(const __half2*)&s0.x);
        float2 b0 = __half22float2(*(const __half2*)&s0.y);
        float2 a1 = __half22float2(*(const __half2*)&s1.x);
        float2 b1 = __half22float2(*(const __half2*)&s1.y);
        acc[0] += a0.x + a1.x; acc[1] += a0.y + a1.y;
        acc[2] += b0.x + b1.x; acc[3] += b0.y + b1.y;
    }
    if (e < e1) {
        uint2 s = xp[(size_t)g_nbr[e] * 32 + lane];
        float2 a = __half22float2(*(const __half2*)&s.x);
        float2 b = __half22float2(*(const __half2*)&s.y);
        acc[0] += a.x; acc[1] += a.y; acc[2] += b.x; acc[3] += b.y;
    }
    __half2 p0 = __floats2half2_rn(acc[0], acc[1]);
    __half2 p1 = __floats2half2_rn(acc[2], acc[3]);
    uint2 pk; pk.x = *(uint32_t*)&p0; pk.y = *(uint32_t*)&p1;
    ((uint2*)out)[(size_t)w * 32 + lane] = pk;
}

__global__ void k_gather256h(const __half* __restrict__ xin, __half* __restrict__ out, int N)
{
    if (blockIdx.x == 0) { g_colsum[threadIdx.x] = 0.f; g_colsq[threadIdx.x] = 0.f; }
    int gt = blockIdx.x * blockDim.x + threadIdx.x;
    int w = gt >> 5, lane = gt & 31;
    if (w >= N) return;
    const uint4* xp = (const uint4*)xin;
    float acc[8];
    {
        uint4 s = xp[(size_t)w * 32 + lane];
        float2 a = __half22float2(*(const __half2*)&s.x);
        float2 b = __half22float2(*(const __half2*)&s.y);
        float2 c = __half22float2(*(const __half2*)&s.z);
        float2 d = __half22float2(*(const __half2*)&s.w);
        acc[0] = a.x; acc[1] = a.y; acc[2] = b.x; acc[3] = b.y;
        acc[4] = c.x; acc[5] = c.y; acc[6] = d.x; acc[7] = d.y;
    }
    int e = g_off[w], e1 = g_off[w + 1];
    for (; e + 1 < e1; e += 2) {
        uint4 s0 = xp[(size_t)g_nbr[e] * 32 + lane];
        uint4 s1 = xp[(size_t)g_nbr[e + 1] * 32 + lane];
        float2 a0 = __half22float2(*(const __half2*)&s0.x);
        float2 b0 = __half22float2(*(const __half2*)&s0.y);
        float2 c0 = __half22float2(*(const __half2*)&s0.z);
        float2 d0 = __half22float2(*(const __half2*)&s0.w);
        float2 a1 = __half22float2(*(const __half2*)&s1.x);
        float2 b1 = __half22float2(*(const __half2*)&s1.y);
        float2 c1 = __half22float2(*(const __half2*)&s1.z);
        float2 d1 = __half22float2(*(const __half2*)&s1.w);
        acc[0] += a0.x + a1.x; acc[1] += a0.y + a1.y;
        acc[2] += b0.x + b1.x; acc[3] += b0.y + b1.y;
        acc[4] += c0.x + c1.x; acc[5] += c0.y + c1.y;
        acc[6] += d0.x + d1.x; acc[7] += d0.y + d1.y;
    }
    if (e < e1) {
        uint4 s = xp[(size_t)g_nbr[e] * 32 + lane];
        float2 a = __half22float2(*(const __half2*)&s.x);
        float2 b = __half22float2(*(const __half2*)&s.y);
        float2 c = __half22float2(*(const __half2*)&s.z);
        float2 d = __half22float2(*(const __half2*)&s.w);
        acc[0] += a.x; acc[1] += a.y; acc[2] += b.x; acc[3] += b.y;
        acc[4] += c.x; acc[5] += c.y; acc[6] += d.x; acc[7] += d.y;
    }
    __half2 p0 = __floats2half2_rn(acc[0], acc[1]);
    __half2 p1 = __floats2half2_rn(acc[2], acc[3]);
    __half2 p2 = __floats2half2_rn(acc[4], acc[5]);
    __half2 p3 = __floats2half2_rn(acc[6], acc[7]);
    uint4 pk;
    pk.x = *(uint32_t*)&p0; pk.y = *(uint32_t*)&p1;
    pk.z = *(uint32_t*)&p2; pk.w = *(uint32_t*)&p3;
    ((uint4*)out)[(size_t)w * 32 + lane] = pk;
}

// ---------------- fp16 tensor-core GEMM: ldmatrix frags, fp16 H out ----------------
#define MMA_F16(d, a, b)                                                          \
    asm volatile("mma.sync.aligned.m16n8k16.row.col.f32.f16.f16.f32 "            \
                 "{%0,%1,%2,%3}, {%4,%5,%6,%7}, {%8,%9}, {%0,%1,%2,%3};"         \
                 : "+f"(d[0]), "+f"(d[1]), "+f"(d[2]), "+f"(d[3])                 \
                 : "r"(a[0]), "r"(a[1]), "r"(a[2]), "r"(a[3]),                    \
                   "r"(b[0]), "r"(b[1]))

template <int K>
__launch_bounds__(256, 2)
__global__ void k_gemm(const __half* __restrict__ A, const __half* __restrict__ Wt,
                       const float* __restrict__ bias, __half* __restrict__ Hout, int M)
{
    const int BM = 128, BN = 128, BK = 32;
    const int NIT = K / BK;
    const int LDA = 40;
    __shared__ __half As[2][BM][LDA];
    __shared__ __half Bs[2][BN][LDA];
    __shared__ float RedS[BN], RedQ[BN];

    int bm = blockIdx.x * BM, bn = blockIdx.y * BN;
    int t = threadIdx.x, lane = t & 31, w = t >> 5;
    int m_warp = (w & 1) * 64;
    int n_warp = (w >> 1) * 32;

    // staging map
    int r0 = t >> 2, s0 = (t & 3) * 8;
    int r1 = (t + 256) >> 2, s1 = s0;
    int gA0 = bm + r0, gA1 = bm + r1;
    int az0 = (gA0 < M) ? 16 : 0, az1 = (gA1 < M) ? 16 : 0;
    const __half* apB0 = A + (size_t)gA0 * K + s0;
    const __half* apB1 = A + (size_t)gA1 * K + s1;
    const __half* bpB0 = Wt + (size_t)(bn + r0) * K + s0;
    const __half* bpB1 = Wt + (size_t)(bn + r1) * K + s1;

    // ldmatrix per-lane offsets (bytes)
    uint32_t sAb = (uint32_t)__cvta_generic_to_shared(&As[0][0][0]);
    uint32_t sBb = (uint32_t)__cvta_generic_to_shared(&Bs[0][0][0]);
    uint32_t offA[4], offB[2];
#pragma unroll
    for (int mt = 0; mt < 4; mt++)
        offA[mt] = (uint32_t)(((m_warp + mt * 16 + (lane & 15)) * LDA + (lane >> 4) * 8) * 2);
#pragma unroll
    for (int p = 0; p < 2; p++)
        offB[p] = (uint32_t)(((n_warp + p * 16 + (lane & 7) + (lane >> 4) * 8) * LDA
                             + ((lane >> 3) & 1) * 8) * 2);

    float acc[4][4][4];
#pragma unroll
    for (int mt = 0; mt < 4; mt++)
#pragma unroll
        for (int nt = 0; nt < 4; nt++)
#pragma unroll
            for (int f = 0; f < 4; f++) acc[mt][nt][f] = 0.f;

    // stage tile 0
    cp16(&As[0][r0][s0], apB0, az0);
    cp16(&As[0][r1][s1], apB1, az1);
    cp16(&Bs[0][r0][s0], bpB0, 16);
    cp16(&Bs[0][r1][s1], bpB1, 16);
    CP_COMMIT();

    for (int it = 0; it < NIT; it++) {
        int buf = it & 1;
        if (it + 1 < NIT) {
            int k0 = (it + 1) * BK;
            cp16(&As[buf ^ 1][r0][s0], apB0 + k0, az0);
            cp16(&As[buf ^ 1][r1][s1], apB1 + k0, az1);
            cp16(&Bs[buf ^ 1][r0][s0], bpB0 + k0, 16);
            cp16(&Bs[buf ^ 1][r1][s1], bpB1 + k0, 16);
            CP_COMMIT();
            CP_WAIT1();
        } else {
            CP_WAIT0();
        }
        __syncthreads();

        uint32_t bA = sAb + (uint32_t)buf * (BM * LDA * 2);
        uint32_t bB = sBb + (uint32_t)buf * (BN * LDA * 2);
#pragma unroll
        for (int ks = 0; ks < 2; ks++) {
            uint32_t kb = (uint32_t)(ks * 16 * 2);
            uint32_t af[4][4], bf[4][2];
#pragma unroll
            for (int mt = 0; mt < 4; mt++)
                LDSM_X4(af[mt][0], af[mt][1], af[mt][2], af[mt][3], bA + offA[mt] + kb);
            LDSM_X4(bf[0][0], bf[0][1], bf[1][0], bf[1][1], bB + offB[0] + kb);
            LDSM_X4(bf[2][0], bf[2][1], bf[3][0], bf[3][1], bB + offB[1] + kb);
#pragma unroll
            for (int mt = 0; mt < 4; mt++)
#pragma unroll
                for (int nt = 0; nt < 4; nt++)
                    MMA_F16(acc[mt][nt], af[mt], bf[nt]);
        }
        __syncthreads();
    }

    // ---- epilogue: bias, fp16 store, per-column sum/sumsq (fp32, exact) ----
    if (t < BN) { RedS[t] = 0.f; RedQ[t] = 0.f; }
    __syncthreads();

    int ar = lane >> 2;
    int ac2 = (lane & 3) * 2;
#pragma unroll
    for (int nt = 0; nt < 4; nt++) {
        int cc = n_warp + nt * 8 + ac2;
        float b0 = bias[bn + cc], b1 = bias[bn + cc + 1];
        float s0a = 0.f, q0 = 0.f, s1a = 0.f, q1 = 0.f;
#pragma unroll
        for (int mt = 0; mt < 4; mt++) {
            int gr0 = bm + m_warp + mt * 16 + ar;
            int gr1 = gr0 + 8;
            if (gr0 < M) {
                float o0 = acc[mt][nt][0] + b0;
                float o1 = acc[mt][nt][1] + b1;
                *(__half2*)(Hout + (size_t)gr0 * HD + bn + cc) = __floats2half2_rn(o0, o1);
                s0a += o0; q0 += o0 * o0; s1a += o1; q1 += o1 * o1;
            }
            if (gr1 < M) {
                float o2 = acc[mt][nt][2] + b0;
                float o3 = acc[mt][nt][3] + b1;
                *(__half2*)(Hout + (size_t)gr1 * HD + bn + cc) = __floats2half2_rn(o2, o3);
                s0a += o2; q0 += o2 * o2; s1a += o3; q1 += o3 * o3;
            }
        }
        atomicAdd(&RedS[cc], s0a);
        atomicAdd(&RedQ[cc], q0);
        atomicAdd(&RedS[cc + 1], s1a);
        atomicAdd(&RedQ[cc + 1], q1);
    }
    __syncthreads();
    if (t < BN) {
        atomicAdd(&g_colsum[bn + t], RedS[t]);
        atomicAdd(&g_colsq[bn + t],  RedQ[t]);
    }
}

// ---------------- BN + ReLU (+ fp16 residual), fp16 in/out; zeroes pool ----------------
__global__ void k_bnrelu_h(const __half* __restrict__ Hin, const float* __restrict__ gam,
                           const float* __restrict__ bet, const __half* __restrict__ resid,
                           __half* __restrict__ out, int M)
{
    // fold pool/cnt zeroing into first 64 blocks (pool consumed only after layer-3 call)
    if (blockIdx.x < 64) {
        g_pool[blockIdx.x * 256 + threadIdx.x] = 0.f;
        if (blockIdx.x == 0 && threadIdx.x < NGR) g_cnt[threadIdx.x] = 0.f;
    }
    int idx = blockIdx.x * blockDim.x + threadIdx.x;   // 8 elems each
    if (idx >= M * 32) return;
    int c8 = (idx & 31) * 8;
    float invN = 1.0f / (float)M;
    uint4 hh = ((const uint4*)Hin)[idx];
    float2 h0 = __half22float2(*(const __half2*)&hh.x);
    float2 h1 = __half22float2(*(const __half2*)&hh.y);
    float2 h2 = __half22float2(*(const __half2*)&hh.z);
    float2 h3 = __half22float2(*(const __half2*)&hh.w);
    float hv[8] = { h0.x, h0.y, h1.x, h1.y, h2.x, h2.y, h3.x, h3.y };
    float o[8];
#pragma unroll
    for (int j = 0; j < 8; j++) {
        int c = c8 + j;
        float m = g_colsum[c] * invN;
        float v = fmaf(-m, m, g_colsq[c] * invN);
        float sc = gam[c] * rsqrtf(v + 1e-5f);
        float sh = fmaf(-m, sc, bet[c]);
        o[j] = fmaxf(fmaf(hv[j], sc, sh), 0.0f);
    }
    if (resid) {
        uint4 r = ((const uint4*)resid)[idx];
        float2 r0 = __half22float2(*(const __half2*)&r.x);
        float2 r1 = __half22float2(*(const __half2*)&r.y);
        float2 r2 = __half22float2(*(const __half2*)&r.z);
        float2 r3 = __half22float2(*(const __half2*)&r.w);
        o[0] += r0.x; o[1] += r0.y; o[2] += r1.x; o[3] += r1.y;
        o[4] += r2.x; o[5] += r2.y; o[6] += r3.x; o[7] += r3.y;
    }
    __half2 p0 = __floats2half2_rn(o[0], o[1]);
    __half2 p1 = __floats2half2_rn(o[2], o[3]);
    __half2 p2 = __floats2half2_rn(o[4], o[5]);
    __half2 p3 = __floats2half2_rn(o[6], o[7]);
    uint4 pk;
    pk.x = *(uint32_t*)&p0; pk.y = *(uint32_t*)&p1;
    pk.z = *(uint32_t*)&p2; pk.w = *(uint32_t*)&p3;
    ((uint4*)out)[idx] = pk;
}

// ---------------- pool: batch sorted -> register-accumulate, flush on change ----------------
__global__ void k_pool2(const __half* __restrict__ x3, int N)
{
    __shared__ int sb[128];
    int n0 = blockIdx.x * 128;
    int n1 = n0 + 128; if (n1 > N) n1 = N;
    int t = threadIdx.x;
    if (t < n1 - n0) sb[t] = g_batch[n0 + t];
    __syncthreads();
    if (n1 <= n0) return;
    float acc = 0.f;
    int curg = sb[0], cnt = 0;
    for (int n = n0; n < n1; n++) {
        int g = sb[n - n0];
        if (g != curg) {
            atomicAdd(&g_pool[curg * HD + t], acc);
            if (t == 0) atomicAdd(&g_cnt[curg], (float)cnt);
            acc = 0.f; cnt = 0; curg = g;
        }
        acc += __half2float(x3[(size_t)n * HD + t]);
        cnt++;
    }
    atomicAdd(&g_pool[curg * HD + t], acc);
    if (t == 0) atomicAdd(&g_cnt[curg], (float)cnt);
}

// ---------------- final MLP head (64 graphs) ----------------
__global__ void k_final(const float* __restrict__ fcW1, const float* __restrict__ fcb1,
                        const float* __restrict__ fcW2, const float* __restrict__ fcb2,
                        float* __restrict__ out)
{
    __shared__ float prow[HD];
    __shared__ float hred[HD];
    int g = blockIdx.x, t = threadIdx.x;
    float cnt = fmaxf(g_cnt[g], 1.0f);
    prow[t] = g_pool[g * HD + t] / cnt;
    __syncthreads();
    float acc = fcb1[t];
    for (int k = 0; k < HD; k++)
        acc = fmaf(prow[k], __ldg(fcW1 + (size_t)k * HD + t), acc);
    float h = fmaxf(acc, 0.0f);
    hred[t] = h * fcW2[t];
    __syncthreads();
    for (int s = HD / 2; s > 0; s >>= 1) {
        if (t < s) hred[t] += hred[t + s];
        __syncthreads();
    }
    if (t == 0) out[g] = hred[0] + fcb2[0];
}

// ---------------- launch ----------------
extern "C" void kernel_launch(void* const* d_in, const int* in_sizes, int n_in,
                              void* d_out, int out_size)
{
    int base = 3;
    if (n_in >= 20 && in_sizes[3] == 1) base = 4;

    const float* x   = (const float*)d_in[0];
    const int*   ei  = (const int*)d_in[1];
    const int*   bat = (const int*)d_in[2];
    const float* W1  = (const float*)d_in[base + 0];
    const float* b1  = (const float*)d_in[base + 1];
    const float* W2  = (const float*)d_in[base + 2];
    const float* b2  = (const float*)d_in[base + 3];
    const float* W3  = (const float*)d_in[base + 4];
    const float* b3  = (const float*)d_in[base + 5];
    const float* ga1 = (const float*)d_in[base + 6];
    const float* be1 = (const float*)d_in[base + 7];
    const float* ga2 = (const float*)d_in[base + 8];
    const float* be2 = (const float*)d_in[base + 9];
    const float* ga3 = (const float*)d_in[base + 10];
    const float* be3 = (const float*)d_in[base + 11];
    const float* fcW1 = (const float*)d_in[base + 12];
    const float* fcb1 = (const float*)d_in[base + 13];
    const float* fcW2 = (const float*)d_in[base + 14];
    const float* fcb2 = (const float*)d_in[base + 15];

    int N = in_sizes[0] / 128;
    int E = in_sizes[1] / 2;

    void* p;
    __half *aggh, *xah, *xbh, *w1t, *w2t, *w3t, *hh;
    cudaGetSymbolAddress(&p, g_aggh); aggh = (__half*)p;
    cudaGetSymbolAddress(&p, g_hbuf); hh   = (__half*)p;
    cudaGetSymbolAddress(&p, g_xah);  xah  = (__half*)p;
    cudaGetSymbolAddress(&p, g_xbh);  xbh  = (__half*)p;
    cudaGetSymbolAddress(&p, g_w1t);  w1t  = (__half*)p;
    cudaGetSymbolAddress(&p, g_w2t);  w2t  = (__half*)p;
    cudaGetSymbolAddress(&p, g_w3t);  w3t  = (__half*)p;
    void* pdeg;
    cudaGetSymbolAddress(&pdeg, g_deg);

    const int tb = 256;
    int ebl = (E + tb - 1) / tb;
    int nb256 = (N + 255) / 256;
    int wbl = (N * 32 + tb - 1) / tb;
    int bnbl = (N * 32 + tb - 1) / tb;
    int nx = (N * 32 + 255) / 256;
    dim3 ggrid((N + 127) / 128, 2);

    // CSR + prep
    cudaMemsetAsync(pdeg, 0, (size_t)N * sizeof(int));
    k_convert<<<ebl, tb>>>(ei, bat, E, N);
    k_prep<<<nx + 768, 256>>>(x, W1, W2, W3, N, nx);
    k_bsum<<<nb256, 256>>>(N);
    k_bscan<<<1, 256>>>(nb256);
    k_off<<<nb256, 256>>>(N);
    k_fill<<<ebl, tb>>>(E);

    // layer 1: K=128
    k_gather128h<<<wbl, tb>>>(aggh, N);
    k_gemm<128><<<ggrid, 256>>>(aggh, w1t, b1, hh, N);
    k_bnrelu_h<<<bnbl, tb>>>(hh, ga1, be1, nullptr, xah, N);

    // layer 2
    k_gather256h<<<wbl, tb>>>(xah, aggh, N);
    k_gemm<256><<<ggrid, 256>>>(aggh, w2t, b2, hh, N);
    k_bnrelu_h<<<bnbl, tb>>>(hh, ga2, be2, xah, xbh, N);

    // layer 3
    k_gather256h<<<wbl, tb>>>(xbh, aggh, N);
    k_gemm<256><<<ggrid, 256>>>(aggh, w3t, b3, hh, N);
    k_bnrelu_h<<<bnbl, tb>>>(hh, ga3, be3, xbh, xah, N);

    // pool + head
    k_pool2<<<(N + 127) / 128, 256>>>(xah, N);
    k_final<<<NGR, 256>>>(fcW1, fcb1, fcW2, fcb2, (float*)d_out);
}